// round 1
// baseline (speedup 1.0000x reference)
#include <cuda_runtime.h>

typedef unsigned long long ull;

// Shapes (fixed by the problem)
#define BB    64
#define NN    256
#define VD    2048
#define LRD   64      // per-branch low-rank dim; concatenated -> 128
#define EMB   1024
#define MTOT  (BB*NN) // 16384

// ---------------- scratch (no allocations allowed) ----------------
__device__ float g_scale[128];            // g/||v|| for U1 (0..63) and U2 (64..127)
__device__ float g_bias[128];             // b1 ‖ b2
__device__ float g_LR[MTOT * 128];        // relu(V@Wcat^T + b): cols 0..63 = right(U1), 64..127 = left(U2)  (8 MB)
__device__ float g_S[BB * NN];            // per-batch column means of uncorr
__device__ float g_feats[BB * VD];        // [64,2048]
__device__ float g_P[8 * BB * EMB];       // split-K partials for final GEMM (2 MB)

// ---------------- packed f32x2 helpers ----------------
__device__ __forceinline__ ull dup2(float a) {
    ull r; unsigned int u = __float_as_uint(a);
    asm("mov.b64 %0, {%1, %1};" : "=l"(r) : "r"(u));
    return r;
}
__device__ __forceinline__ ull pack2(float x, float y) {
    ull r; asm("mov.b64 %0, {%1, %2};" : "=l"(r) : "r"(__float_as_uint(x)), "r"(__float_as_uint(y)));
    return r;
}
__device__ __forceinline__ void fma2(ull& c, ull a, ull b) {
    asm("fma.rn.f32x2 %0, %1, %2, %0;" : "+l"(c) : "l"(a), "l"(b));
}
__device__ __forceinline__ float2 unpack2(ull c) {
    unsigned int lo, hi;
    asm("mov.b64 {%0, %1}, %2;" : "=r"(lo), "=r"(hi) : "l"(c));
    float2 f; f.x = __uint_as_float(lo); f.y = __uint_as_float(hi);
    return f;
}

// ---------------- Kernel A: weight-norm scale/bias prep ----------------
// 128 rows, one warp per row. scale[k] = g[k] / ||v_k||, bias concat.
__global__ void k_prep(const float* __restrict__ U1v, const float* __restrict__ U1g,
                       const float* __restrict__ U1b, const float* __restrict__ U2v,
                       const float* __restrict__ U2g, const float* __restrict__ U2b)
{
    int w = blockIdx.x * 4 + (threadIdx.x >> 5);   // 0..127
    int lane = threadIdx.x & 31;
    const float* v = (w < 64) ? (U1v + w * VD) : (U2v + (w - 64) * VD);
    float ss = 0.f;
    for (int j = lane; j < VD; j += 32) { float x = v[j]; ss = fmaf(x, x, ss); }
    #pragma unroll
    for (int o = 16; o > 0; o >>= 1) ss += __shfl_xor_sync(0xffffffffu, ss, o);
    if (lane == 0) {
        float gg = (w < 64) ? U1g[w] : U2g[w - 64];
        float bb = (w < 64) ? U1b[w] : U2b[w - 64];
        g_scale[w] = gg / sqrtf(ss);
        g_bias[w]  = bb;
    }
}

// ---------------- Kernel B: big GEMM  [16384,2048] x [128,2048]^T ----------------
// BM=64, BN=128 (full), BK=16, 256 threads, 4x8 per thread, packed f32x2 FMA.
// Epilogue: relu(acc*scale + bias) -> g_LR
__global__ __launch_bounds__(256) void k_gemm1(const float* __restrict__ A,
                                               const float* __restrict__ U1,
                                               const float* __restrict__ U2)
{
    __shared__ float sA[2][16][64];
    __shared__ float sB[2][16][128];
    const int t = threadIdx.x;
    const int tx = t & 15, ty = t >> 4;
    const int blockRow = blockIdx.x * 64;

    const int arow = t >> 2, ak = (t & 3) * 4;   // A tile load: 64 rows x 16 k
    const int brow = t >> 1, bk = (t & 1) * 8;   // B tile load: 128 rows x 16 k
    const float* Ap = A + (blockRow + arow) * VD + ak;
    const float* Bp = ((brow < 64) ? (U1 + brow * VD) : (U2 + (brow - 64) * VD)) + bk;

    ull acc[4][4];
    #pragma unroll
    for (int i = 0; i < 4; i++)
        #pragma unroll
        for (int j = 0; j < 4; j++) acc[i][j] = 0ull;

    float4 ar  = *(const float4*)Ap;
    float4 br0 = *(const float4*)Bp;
    float4 br1 = *(const float4*)(Bp + 4);
    sA[0][ak+0][arow]=ar.x;  sA[0][ak+1][arow]=ar.y;  sA[0][ak+2][arow]=ar.z;  sA[0][ak+3][arow]=ar.w;
    sB[0][bk+0][brow]=br0.x; sB[0][bk+1][brow]=br0.y; sB[0][bk+2][brow]=br0.z; sB[0][bk+3][brow]=br0.w;
    sB[0][bk+4][brow]=br1.x; sB[0][bk+5][brow]=br1.y; sB[0][bk+6][brow]=br1.z; sB[0][bk+7][brow]=br1.w;
    __syncthreads();

    const int NT = VD / 16; // 128 tiles
    for (int tile = 0; tile < NT; ++tile) {
        const int buf = tile & 1;
        if (tile + 1 < NT) {
            ar  = *(const float4*)(Ap + (tile + 1) * 16);
            br0 = *(const float4*)(Bp + (tile + 1) * 16);
            br1 = *(const float4*)(Bp + (tile + 1) * 16 + 4);
        }
        #pragma unroll
        for (int k = 0; k < 16; k++) {
            float4 a4  = *(const float4*)&sA[buf][k][ty * 4];
            float4 b4a = *(const float4*)&sB[buf][k][tx * 8];
            float4 b4b = *(const float4*)&sB[buf][k][tx * 8 + 4];
            ull a2[4] = { dup2(a4.x), dup2(a4.y), dup2(a4.z), dup2(a4.w) };
            ull bb2[4] = { pack2(b4a.x, b4a.y), pack2(b4a.z, b4a.w),
                           pack2(b4b.x, b4b.y), pack2(b4b.z, b4b.w) };
            #pragma unroll
            for (int i = 0; i < 4; i++)
                #pragma unroll
                for (int j = 0; j < 4; j++) fma2(acc[i][j], a2[i], bb2[j]);
        }
        if (tile + 1 < NT) {
            const int nb = buf ^ 1;
            sA[nb][ak+0][arow]=ar.x;  sA[nb][ak+1][arow]=ar.y;  sA[nb][ak+2][arow]=ar.z;  sA[nb][ak+3][arow]=ar.w;
            sB[nb][bk+0][brow]=br0.x; sB[nb][bk+1][brow]=br0.y; sB[nb][bk+2][brow]=br0.z; sB[nb][bk+3][brow]=br0.w;
            sB[nb][bk+4][brow]=br1.x; sB[nb][bk+5][brow]=br1.y; sB[nb][bk+6][brow]=br1.z; sB[nb][bk+7][brow]=br1.w;
            __syncthreads();
        }
    }

    float sc[8], bi[8];
    #pragma unroll
    for (int j = 0; j < 8; j++) { sc[j] = g_scale[tx * 8 + j]; bi[j] = g_bias[tx * 8 + j]; }
    #pragma unroll
    for (int i = 0; i < 4; i++) {
        float* orow = g_LR + (blockRow + ty * 4 + i) * 128 + tx * 8;
        #pragma unroll
        for (int j = 0; j < 4; j++) {
            float2 c = unpack2(acc[i][j]);
            float2 r;
            r.x = fmaxf(fmaf(c.x, sc[2 * j],     bi[2 * j]),     0.f);
            r.y = fmaxf(fmaf(c.y, sc[2 * j + 1], bi[2 * j + 1]), 0.f);
            *(float2*)(orow + 2 * j) = r;
        }
    }
}

// ---------------- Kernel C: per-batch d, u, s (the collapsed NxN math) ----------------
// One block per batch. cols 0..63 = right (U1 path), 64..127 = left (U2 path).
__global__ __launch_bounds__(256) void k_corr()
{
    __shared__ float d_s[256];
    __shared__ float upart[4][64];
    __shared__ float u_s[64];
    const int b = blockIdx.x, t = threadIdx.x;
    const float* myrow = g_LR + (b * NN + t) * 128;

    // d[n] = rsqrt(<left_n, right_n> + 1e-6)
    float dot = 0.f;
    #pragma unroll
    for (int i = 0; i < 16; i++) {
        float4 r = ((const float4*)myrow)[i];
        float4 l = ((const float4*)myrow)[16 + i];
        dot += r.x * l.x + r.y * l.y + r.z * l.z + r.w * l.w;
    }
    const float dv = rsqrtf(dot + 1e-6f);
    d_s[t] = dv;
    __syncthreads();

    // u[k] = sum_n d[n]*left[n,k]  (4 partial groups over n)
    const int k = t & 63, g = t >> 6;
    float part = 0.f;
    const float* lbase = g_LR + (b * NN + g * 64) * 128 + 64 + k;
    #pragma unroll 4
    for (int n = 0; n < 64; n++)
        part = fmaf(d_s[g * 64 + n], lbase[n * 128], part);
    upart[g][k] = part;
    __syncthreads();
    if (t < 64) u_s[t] = upart[0][t] + upart[1][t] + upart[2][t] + upart[3][t];
    __syncthreads();

    // s[m] = 1 + 1/N - (d[m]/N) * <u, right_m>
    float sm = 0.f;
    #pragma unroll
    for (int kk = 0; kk < 64; kk++) sm = fmaf(u_s[kk], myrow[kk], sm);
    g_S[b * NN + t] = 1.f + (1.f / 256.f) - (dv * (1.f / 256.f)) * sm;
}

// ---------------- Kernel D: feats[b,v] = sum_m s[b,m] * V[b,m,v]  (134 MB stream) ----------------
__global__ __launch_bounds__(256) void k_feats(const float* __restrict__ V)
{
    __shared__ float ss[256];
    const int b = blockIdx.y;
    const int tid = threadIdx.x;
    ss[tid] = g_S[b * NN + tid];
    __syncthreads();
    const int v0 = (blockIdx.x * 256 + tid) * 4;
    const float* base = V + (size_t)b * NN * VD + v0;
    float4 acc = make_float4(0.f, 0.f, 0.f, 0.f);
    #pragma unroll 4
    for (int m = 0; m < NN; m++) {
        float4 val = *(const float4*)(base + (size_t)m * VD);
        float sv = ss[m];
        acc.x = fmaf(sv, val.x, acc.x);
        acc.y = fmaf(sv, val.y, acc.y);
        acc.z = fmaf(sv, val.z, acc.z);
        acc.w = fmaf(sv, val.w, acc.w);
    }
    *(float4*)(g_feats + b * VD + v0) = acc;
}

// ---------------- Kernel E: split-K GEMM  x = feats @ W^T  ->  partials g_P ----------------
// grid (16 e-tiles, 8 k-splits); BM=64(all b), BN=64, BK=32; 4x4 per thread.
__global__ __launch_bounds__(256) void k_gemm2(const float* __restrict__ W)
{
    __shared__ float sA[32][65];
    __shared__ float sB[32][65];
    const int t = threadIdx.x;
    const int tx = t & 15, ty = t >> 4;
    const int e0 = blockIdx.x * 64;
    const int k0 = blockIdx.y * 256;
    const int lrow = t >> 2, lk = (t & 3) * 8;
    float acc[4][4] = {};

    for (int stage = 0; stage < 8; ++stage) {
        const int kb = k0 + stage * 32;
        float4 a0 = *(const float4*)(g_feats + lrow * VD + kb + lk);
        float4 a1 = *(const float4*)(g_feats + lrow * VD + kb + lk + 4);
        float4 w0 = *(const float4*)(W + (e0 + lrow) * VD + kb + lk);
        float4 w1 = *(const float4*)(W + (e0 + lrow) * VD + kb + lk + 4);
        __syncthreads();
        sA[lk+0][lrow]=a0.x; sA[lk+1][lrow]=a0.y; sA[lk+2][lrow]=a0.z; sA[lk+3][lrow]=a0.w;
        sA[lk+4][lrow]=a1.x; sA[lk+5][lrow]=a1.y; sA[lk+6][lrow]=a1.z; sA[lk+7][lrow]=a1.w;
        sB[lk+0][lrow]=w0.x; sB[lk+1][lrow]=w0.y; sB[lk+2][lrow]=w0.z; sB[lk+3][lrow]=w0.w;
        sB[lk+4][lrow]=w1.x; sB[lk+5][lrow]=w1.y; sB[lk+6][lrow]=w1.z; sB[lk+7][lrow]=w1.w;
        __syncthreads();
        #pragma unroll
        for (int k = 0; k < 32; k++) {
            float av[4], bv[4];
            #pragma unroll
            for (int i = 0; i < 4; i++) av[i] = sA[k][ty * 4 + i];
            #pragma unroll
            for (int j = 0; j < 4; j++) bv[j] = sB[k][tx * 4 + j];
            #pragma unroll
            for (int i = 0; i < 4; i++)
                #pragma unroll
                for (int j = 0; j < 4; j++) acc[i][j] = fmaf(av[i], bv[j], acc[i][j]);
        }
    }
    #pragma unroll
    for (int i = 0; i < 4; i++)
        #pragma unroll
        for (int j = 0; j < 4; j++)
            g_P[(blockIdx.y * 64 + ty * 4 + i) * EMB + e0 + tx * 4 + j] = acc[i][j];
}

// ---------------- Kernel F: reduce split-K + BatchNorm (training-mode, biased var) ----------------
__global__ __launch_bounds__(256) void k_bn(const float* __restrict__ b_lin,
                                            const float* __restrict__ gamma,
                                            const float* __restrict__ beta,
                                            float* __restrict__ out)
{
    const int e = blockIdx.x * 256 + threadIdx.x;
    const float bias = b_lin[e];
    float acc = 0.f;
    for (int b = 0; b < BB; b++) {
        float x = bias;
        #pragma unroll
        for (int s = 0; s < 8; s++) x += g_P[(s * BB + b) * EMB + e];
        acc += x;
    }
    const float mu = acc * (1.f / BB);
    float acc2 = 0.f;
    for (int b = 0; b < BB; b++) {
        float x = bias;
        #pragma unroll
        for (int s = 0; s < 8; s++) x += g_P[(s * BB + b) * EMB + e];
        float dd = x - mu; acc2 = fmaf(dd, dd, acc2);
    }
    const float inv = rsqrtf(acc2 * (1.f / BB) + 1e-5f);
    const float ga = gamma[e], be = beta[e];
    for (int b = 0; b < BB; b++) {
        float x = bias;
        #pragma unroll
        for (int s = 0; s < 8; s++) x += g_P[(s * BB + b) * EMB + e];
        out[b * EMB + e] = fmaf(ga * (x - mu), inv, be);
    }
}

// ---------------- launch ----------------
extern "C" void kernel_launch(void* const* d_in, const int* in_sizes, int n_in,
                              void* d_out, int out_size)
{
    const float* Vmat = (const float*)d_in[0];
    const float* U1v  = (const float*)d_in[1];
    const float* U1g  = (const float*)d_in[2];
    const float* U1b  = (const float*)d_in[3];
    const float* U2v  = (const float*)d_in[4];
    const float* U2g  = (const float*)d_in[5];
    const float* U2b  = (const float*)d_in[6];
    const float* Wl   = (const float*)d_in[7];
    const float* bl   = (const float*)d_in[8];
    const float* gam  = (const float*)d_in[9];
    const float* bet  = (const float*)d_in[10];
    float* out = (float*)d_out;

    k_prep<<<32, 128>>>(U1v, U1g, U1b, U2v, U2g, U2b);
    k_gemm1<<<MTOT / 64, 256>>>(Vmat, U1v, U2v);
    k_corr<<<BB, 256>>>();
    k_feats<<<dim3(VD / 1024, BB), 256>>>(Vmat);
    k_gemm2<<<dim3(EMB / 64, 8), 256>>>(Wl);
    k_bn<<<EMB / 256, 256>>>(bl, gam, bet, out);
}

// round 4
// speedup vs baseline: 2.5134x; 2.5134x over previous
#include <cuda_runtime.h>
#include <cuda_bf16.h>
#include <cstdint>

typedef unsigned long long ull;

// Shapes (fixed by the problem)
#define BB    64
#define NN    256
#define VD    2048
#define EMB   1024
#define MTOT  (BB*NN) // 16384

// ---------------- scratch (no allocations allowed) ----------------
__device__ float g_scale[128];            // g/||v|| for U1 (0..63) and U2 (64..127)
__device__ float g_bias[128];             // b1 ‖ b2
__device__ __nv_bfloat16 g_Bhi[128 * VD]; // weight rows hi (U1 ‖ U2)
__device__ __nv_bfloat16 g_Blo[128 * VD]; // weight rows lo
__device__ float g_LR[MTOT * 128];        // relu(V@Wcat^T + b): cols 0..63 right(U1), 64..127 left(U2)
__device__ float g_S[BB * NN];            // per-batch column means of uncorr
__device__ float g_feats4[4 * BB * VD];   // 4-way m-split partials of feats
__device__ float g_P[8 * BB * EMB];       // split-K partials for final GEMM

// ---------------- Kernel A: weight-norm scale/bias prep ----------------
__global__ void k_prep(const float* __restrict__ U1v, const float* __restrict__ U1g,
                       const float* __restrict__ U1b, const float* __restrict__ U2v,
                       const float* __restrict__ U2g, const float* __restrict__ U2b)
{
    int w = blockIdx.x * 4 + (threadIdx.x >> 5);   // 0..127
    int lane = threadIdx.x & 31;
    const float* v = (w < 64) ? (U1v + w * VD) : (U2v + (w - 64) * VD);
    float ss = 0.f;
    for (int j = lane; j < VD; j += 32) { float x = v[j]; ss = fmaf(x, x, ss); }
    #pragma unroll
    for (int o = 16; o > 0; o >>= 1) ss += __shfl_xor_sync(0xffffffffu, ss, o);
    if (lane == 0) {
        float gg = (w < 64) ? U1g[w] : U2g[w - 64];
        float bb = (w < 64) ? U1b[w] : U2b[w - 64];
        g_scale[w] = gg / sqrtf(ss);
        g_bias[w]  = bb;
    }
}

// ---------------- Kernel A2: split weight rows into bf16 hi/lo ----------------
__global__ void k_convB(const float* __restrict__ U1v, const float* __restrict__ U2v)
{
    int idx = blockIdx.x * 256 + threadIdx.x;      // 0 .. 128*2048-1
    int row = idx >> 11, col = idx & 2047;
    float x = (row < 64) ? U1v[row * VD + col] : U2v[(row - 64) * VD + col];
    __nv_bfloat16 h = __float2bfloat16(x);
    __nv_bfloat16 l = __float2bfloat16(x - __bfloat162float(h));
    g_Bhi[idx] = h;
    g_Blo[idx] = l;
}

// ---------------- mma helpers ----------------
__device__ __forceinline__ void ldsm4(uint32_t& r0, uint32_t& r1, uint32_t& r2, uint32_t& r3, uint32_t a) {
    asm volatile("ldmatrix.sync.aligned.m8n8.x4.shared.b16 {%0,%1,%2,%3}, [%4];"
                 : "=r"(r0), "=r"(r1), "=r"(r2), "=r"(r3) : "r"(a));
}
__device__ __forceinline__ void mma16816(float* d, const uint32_t* a, const uint32_t* b) {
    asm volatile("mma.sync.aligned.m16n8k16.row.col.f32.bf16.bf16.f32 "
                 "{%0,%1,%2,%3},{%4,%5,%6,%7},{%8,%9},{%0,%1,%2,%3};"
                 : "+f"(d[0]), "+f"(d[1]), "+f"(d[2]), "+f"(d[3])
                 : "r"(a[0]), "r"(a[1]), "r"(a[2]), "r"(a[3]), "r"(b[0]), "r"(b[1]));
}
__device__ __forceinline__ void cp16(uint32_t dst, const void* src) {
    asm volatile("cp.async.ca.shared.global [%0], [%1], 16;" :: "r"(dst), "l"(src));
}
__device__ __forceinline__ unsigned short bfbits(__nv_bfloat16 h) {
    return *reinterpret_cast<unsigned short*>(&h);
}

// ---------------- Kernel B: GEMM1 on tensor cores (split-bf16) ----------------
// C[16384,128] = relu( (A[16384,2048] @ Wcat[128,2048]^T) * scale + bias )
// BM=64, BN=128, BK=16, 256 threads (8 warps as 4x2), double-buffered.
// A loaded fp32 -> split hi/lo in regs -> SMEM. B hi/lo streamed via cp.async.
// Products: Ahi*Bhi + Ahi*Blo + Alo*Bhi (fp32 accumulate).
#define AST 24   // smem row stride in bf16 (16 data + 8 pad -> 48B, conflict-free ldmatrix)
__global__ __launch_bounds__(256) void k_gemm1(const float* __restrict__ A)
{
    __shared__ __nv_bfloat16 sAhi[2][64 * AST];
    __shared__ __nv_bfloat16 sAlo[2][64 * AST];
    __shared__ __nv_bfloat16 sBhi[2][128 * AST];
    __shared__ __nv_bfloat16 sBlo[2][128 * AST];

    const int t = threadIdx.x;
    const int lane = t & 31;
    const int warp = t >> 5;
    const int wy = warp & 3;            // M quadrant (16 rows each)
    const int wx = warp >> 2;           // N half (64 cols each)
    const int blockRow = blockIdx.x * 64;

    // load roles
    const int arow = t >> 2, akc = (t & 3) * 4;           // A: 64 rows x 4 float4-chunks
    const int bn = t >> 1, bk8 = (t & 1) * 8;             // B: 128 rows x 2 16B-chunks
    const float* Ap = A + (size_t)(blockRow + arow) * VD + akc;
    const __nv_bfloat16* Bhp = g_Bhi + bn * VD + bk8;
    const __nv_bfloat16* Blp = g_Blo + bn * VD + bk8;

    const uint32_t uAhi = (uint32_t)__cvta_generic_to_shared(&sAhi[0][0]);
    const uint32_t uAlo = (uint32_t)__cvta_generic_to_shared(&sAlo[0][0]);
    const uint32_t uBhi = (uint32_t)__cvta_generic_to_shared(&sBhi[0][0]);
    const uint32_t uBlo = (uint32_t)__cvta_generic_to_shared(&sBlo[0][0]);

    float acc[8][4];
    #pragma unroll
    for (int i = 0; i < 8; i++)
        #pragma unroll
        for (int j = 0; j < 4; j++) acc[i][j] = 0.f;

    // ---- prologue: stage 0 into buffer 0 ----
    {
        cp16(uBhi + (uint32_t)(bn * AST + bk8) * 2, Bhp);
        cp16(uBlo + (uint32_t)(bn * AST + bk8) * 2, Blp);
        float4 av = *(const float4*)Ap;
        __nv_bfloat16 h0 = __float2bfloat16(av.x), h1 = __float2bfloat16(av.y),
                      h2 = __float2bfloat16(av.z), h3 = __float2bfloat16(av.w);
        __nv_bfloat16 l0 = __float2bfloat16(av.x - __bfloat162float(h0)),
                      l1 = __float2bfloat16(av.y - __bfloat162float(h1)),
                      l2 = __float2bfloat16(av.z - __bfloat162float(h2)),
                      l3 = __float2bfloat16(av.w - __bfloat162float(h3));
        ull hp = (ull)bfbits(h0) | ((ull)bfbits(h1) << 16) | ((ull)bfbits(h2) << 32) | ((ull)bfbits(h3) << 48);
        ull lp = (ull)bfbits(l0) | ((ull)bfbits(l1) << 16) | ((ull)bfbits(l2) << 32) | ((ull)bfbits(l3) << 48);
        *(ull*)&sAhi[0][arow * AST + akc] = hp;
        *(ull*)&sAlo[0][arow * AST + akc] = lp;
        asm volatile("cp.async.commit_group;");
        asm volatile("cp.async.wait_group 0;");
        __syncthreads();
    }

    // per-warp ldmatrix addresses (byte offsets within one buffer)
    const uint32_t aoff = (uint32_t)(((wy * 16 + (lane & 15)) * AST + ((lane >> 4) << 3)) * 2);
    uint32_t boff[4];
    #pragma unroll
    for (int p = 0; p < 4; p++) {
        int nrow = wx * 64 + p * 16 + (lane & 7) + ((lane >> 4) << 3);
        boff[p] = (uint32_t)((nrow * AST + (((lane >> 3) & 1) << 3)) * 2);
    }

    const int NS = VD / 16; // 128 stages
    for (int s = 0; s < NS; ++s) {
        const int buf = s & 1, nb = buf ^ 1;
        float4 av;
        if (s + 1 < NS) {
            // issue next-stage loads (overlap with compute)
            cp16(uBhi + (uint32_t)(nb * 128 * AST + bn * AST + bk8) * 2, Bhp + (s + 1) * 16);
            cp16(uBlo + (uint32_t)(nb * 128 * AST + bn * AST + bk8) * 2, Blp + (s + 1) * 16);
            av = *(const float4*)(Ap + (s + 1) * 16);
        }
        asm volatile("cp.async.commit_group;");

        // ---- compute stage s ----
        uint32_t ah[4], al[4];
        const uint32_t abufA = (uint32_t)(buf * 64 * AST * 2);
        const uint32_t abufB = (uint32_t)(buf * 128 * AST * 2);
        ldsm4(ah[0], ah[1], ah[2], ah[3], uAhi + abufA + aoff);
        ldsm4(al[0], al[1], al[2], al[3], uAlo + abufA + aoff);
        uint32_t bh[16], bl[16];
        #pragma unroll
        for (int p = 0; p < 4; p++) {
            ldsm4(bh[p*4+0], bh[p*4+1], bh[p*4+2], bh[p*4+3], uBhi + abufB + boff[p]);
            ldsm4(bl[p*4+0], bl[p*4+1], bl[p*4+2], bl[p*4+3], uBlo + abufB + boff[p]);
        }
        #pragma unroll
        for (int nt = 0; nt < 8; nt++) {
            mma16816(acc[nt], ah, &bh[nt * 2]);
            mma16816(acc[nt], ah, &bl[nt * 2]);
            mma16816(acc[nt], al, &bh[nt * 2]);
        }

        if (s + 1 < NS) {
            __nv_bfloat16 h0 = __float2bfloat16(av.x), h1 = __float2bfloat16(av.y),
                          h2 = __float2bfloat16(av.z), h3 = __float2bfloat16(av.w);
            __nv_bfloat16 l0 = __float2bfloat16(av.x - __bfloat162float(h0)),
                          l1 = __float2bfloat16(av.y - __bfloat162float(h1)),
                          l2 = __float2bfloat16(av.z - __bfloat162float(h2)),
                          l3 = __float2bfloat16(av.w - __bfloat162float(h3));
            ull hp = (ull)bfbits(h0) | ((ull)bfbits(h1) << 16) | ((ull)bfbits(h2) << 32) | ((ull)bfbits(h3) << 48);
            ull lp = (ull)bfbits(l0) | ((ull)bfbits(l1) << 16) | ((ull)bfbits(l2) << 32) | ((ull)bfbits(l3) << 48);
            *(ull*)&sAhi[nb][arow * AST + akc] = hp;
            *(ull*)&sAlo[nb][arow * AST + akc] = lp;
        }
        asm volatile("cp.async.wait_group 0;");
        __syncthreads();
    }

    // ---- epilogue: scale + bias + relu, write g_LR ----
    const int r0 = blockRow + wy * 16 + (lane >> 2);
    #pragma unroll
    for (int nt = 0; nt < 8; nt++) {
        const int col = wx * 64 + nt * 8 + ((lane & 3) << 1);
        const float s0 = g_scale[col], s1 = g_scale[col + 1];
        const float b0 = g_bias[col],  b1 = g_bias[col + 1];
        float2 v;
        v.x = fmaxf(fmaf(acc[nt][0], s0, b0), 0.f);
        v.y = fmaxf(fmaf(acc[nt][1], s1, b1), 0.f);
        *(float2*)&g_LR[(size_t)r0 * 128 + col] = v;
        v.x = fmaxf(fmaf(acc[nt][2], s0, b0), 0.f);
        v.y = fmaxf(fmaf(acc[nt][3], s1, b1), 0.f);
        *(float2*)&g_LR[(size_t)(r0 + 8) * 128 + col] = v;
    }
}

// ---------------- Kernel C: per-batch d, u, s (collapsed NxN math) ----------------
__global__ __launch_bounds__(256) void k_corr()
{
    __shared__ float d_s[256];
    __shared__ float upart[4][64];
    __shared__ float u_s[64];
    const int b = blockIdx.x, t = threadIdx.x;
    const float* myrow = g_LR + (size_t)(b * NN + t) * 128;

    float dot = 0.f;
    #pragma unroll
    for (int i = 0; i < 16; i++) {
        float4 r = ((const float4*)myrow)[i];
        float4 l = ((const float4*)myrow)[16 + i];
        dot += r.x * l.x + r.y * l.y + r.z * l.z + r.w * l.w;
    }
    const float dv = rsqrtf(dot + 1e-6f);
    d_s[t] = dv;
    __syncthreads();

    const int k = t & 63, g = t >> 6;
    float part = 0.f;
    const float* lbase = g_LR + (size_t)(b * NN + g * 64) * 128 + 64 + k;
    #pragma unroll 4
    for (int n = 0; n < 64; n++)
        part = fmaf(d_s[g * 64 + n], lbase[(size_t)n * 128], part);
    upart[g][k] = part;
    __syncthreads();
    if (t < 64) u_s[t] = upart[0][t] + upart[1][t] + upart[2][t] + upart[3][t];
    __syncthreads();

    float sm = 0.f;
    #pragma unroll
    for (int kk = 0; kk < 64; kk++) sm = fmaf(u_s[kk], myrow[kk], sm);
    g_S[b * NN + t] = 1.f + (1.f / 256.f) - (dv * (1.f / 256.f)) * sm;
}

// ---------------- Kernel D: feats partials (m split 4 ways, 512 blocks) ----------------
__global__ __launch_bounds__(256) void k_feats(const float* __restrict__ V)
{
    __shared__ float ss[64];
    const int b = blockIdx.z, q = blockIdx.y;
    const int tid = threadIdx.x;
    if (tid < 64) ss[tid] = g_S[b * NN + q * 64 + tid];
    __syncthreads();
    const int v0 = (blockIdx.x * 256 + tid) * 4;
    const float* base = V + (size_t)b * NN * VD + (size_t)q * 64 * VD + v0;
    float4 acc = make_float4(0.f, 0.f, 0.f, 0.f);
    #pragma unroll 4
    for (int m = 0; m < 64; m++) {
        float4 val = *(const float4*)(base + (size_t)m * VD);
        float sv = ss[m];
        acc.x = fmaf(sv, val.x, acc.x);
        acc.y = fmaf(sv, val.y, acc.y);
        acc.z = fmaf(sv, val.z, acc.z);
        acc.w = fmaf(sv, val.w, acc.w);
    }
    *(float4*)(g_feats4 + (size_t)(q * BB + b) * VD + v0) = acc;
}

// ---------------- Kernel E: split-K GEMM  x = feats @ W^T  ->  partials g_P ----------------
__global__ __launch_bounds__(256) void k_gemm2(const float* __restrict__ W)
{
    __shared__ float sA[32][65];
    __shared__ float sB[32][65];
    const int t = threadIdx.x;
    const int tx = t & 15, ty = t >> 4;
    const int e0 = blockIdx.x * 64;
    const int k0 = blockIdx.y * 256;
    const int lrow = t >> 2, lk = (t & 3) * 8;
    float acc[4][4] = {};

    for (int stage = 0; stage < 8; ++stage) {
        const int kb = k0 + stage * 32;
        float4 a0 = make_float4(0,0,0,0), a1 = make_float4(0,0,0,0);
        #pragma unroll
        for (int p = 0; p < 4; p++) {
            float4 t0 = *(const float4*)(g_feats4 + (size_t)(p * BB + lrow) * VD + kb + lk);
            float4 t1 = *(const float4*)(g_feats4 + (size_t)(p * BB + lrow) * VD + kb + lk + 4);
            a0.x += t0.x; a0.y += t0.y; a0.z += t0.z; a0.w += t0.w;
            a1.x += t1.x; a1.y += t1.y; a1.z += t1.z; a1.w += t1.w;
        }
        float4 w0 = *(const float4*)(W + (size_t)(e0 + lrow) * VD + kb + lk);
        float4 w1 = *(const float4*)(W + (size_t)(e0 + lrow) * VD + kb + lk + 4);
        __syncthreads();
        sA[lk+0][lrow]=a0.x; sA[lk+1][lrow]=a0.y; sA[lk+2][lrow]=a0.z; sA[lk+3][lrow]=a0.w;
        sA[lk+4][lrow]=a1.x; sA[lk+5][lrow]=a1.y; sA[lk+6][lrow]=a1.z; sA[lk+7][lrow]=a1.w;
        sB[lk+0][lrow]=w0.x; sB[lk+1][lrow]=w0.y; sB[lk+2][lrow]=w0.z; sB[lk+3][lrow]=w0.w;
        sB[lk+4][lrow]=w1.x; sB[lk+5][lrow]=w1.y; sB[lk+6][lrow]=w1.z; sB[lk+7][lrow]=w1.w;
        __syncthreads();
        #pragma unroll
        for (int k = 0; k < 32; k++) {
            float av[4], bv[4];
            #pragma unroll
            for (int i = 0; i < 4; i++) av[i] = sA[k][ty * 4 + i];
            #pragma unroll
            for (int j = 0; j < 4; j++) bv[j] = sB[k][tx * 4 + j];
            #pragma unroll
            for (int i = 0; i < 4; i++)
                #pragma unroll
                for (int j = 0; j < 4; j++) acc[i][j] = fmaf(av[i], bv[j], acc[i][j]);
        }
    }
    #pragma unroll
    for (int i = 0; i < 4; i++)
        #pragma unroll
        for (int j = 0; j < 4; j++)
            g_P[(size_t)(blockIdx.y * 64 + ty * 4 + i) * EMB + e0 + tx * 4 + j] = acc[i][j];
}

// ---------------- Kernel F: reduce split-K + BatchNorm ----------------
__global__ __launch_bounds__(256) void k_bn(const float* __restrict__ b_lin,
                                            const float* __restrict__ gamma,
                                            const float* __restrict__ beta,
                                            float* __restrict__ out)
{
    const int e = blockIdx.x * 256 + threadIdx.x;
    const float bias = b_lin[e];
    float acc = 0.f;
    for (int b = 0; b < BB; b++) {
        float x = bias;
        #pragma unroll
        for (int s = 0; s < 8; s++) x += g_P[(size_t)(s * BB + b) * EMB + e];
        acc += x;
    }
    const float mu = acc * (1.f / BB);
    float acc2 = 0.f;
    for (int b = 0; b < BB; b++) {
        float x = bias;
        #pragma unroll
        for (int s = 0; s < 8; s++) x += g_P[(size_t)(s * BB + b) * EMB + e];
        float dd = x - mu; acc2 = fmaf(dd, dd, acc2);
    }
    const float inv = rsqrtf(acc2 * (1.f / BB) + 1e-5f);
    const float ga = gamma[e], be = beta[e];
    for (int b = 0; b < BB; b++) {
        float x = bias;
        #pragma unroll
        for (int s = 0; s < 8; s++) x += g_P[(size_t)(s * BB + b) * EMB + e];
        out[b * EMB + e] = fmaf(ga * (x - mu), inv, be);
    }
}

// ---------------- launch ----------------
extern "C" void kernel_launch(void* const* d_in, const int* in_sizes, int n_in,
                              void* d_out, int out_size)
{
    const float* Vmat = (const float*)d_in[0];
    const float* U1v  = (const float*)d_in[1];
    const float* U1g  = (const float*)d_in[2];
    const float* U1b  = (const float*)d_in[3];
    const float* U2v  = (const float*)d_in[4];
    const float* U2g  = (const float*)d_in[5];
    const float* U2b  = (const float*)d_in[6];
    const float* Wl   = (const float*)d_in[7];
    const float* bl   = (const float*)d_in[8];
    const float* gam  = (const float*)d_in[9];
    const float* bet  = (const float*)d_in[10];
    float* out = (float*)d_out;

    k_prep<<<32, 128>>>(U1v, U1g, U1b, U2v, U2g, U2b);
    k_convB<<<(128 * VD) / 256, 256>>>(U1v, U2v);
    k_gemm1<<<MTOT / 64, 256>>>(Vmat);
    k_corr<<<BB, 256>>>();
    k_feats<<<dim3(2, 4, BB), 256>>>(Vmat);
    k_gemm2<<<dim3(EMB / 64, 8), 256>>>(Wl);
    k_bn<<<EMB / 256, 256>>>(bl, gam, bet, out);
}

// round 8
// speedup vs baseline: 3.6668x; 1.4589x over previous
#include <cuda_runtime.h>
#include <cuda_bf16.h>
#include <cstdint>

typedef unsigned long long ull;

// Shapes (fixed by the problem)
#define BB    64
#define NN    256
#define VD    2048
#define EMB   1024
#define MTOT  (BB*NN) // 16384
#define NSG   (VD/16) // 128 gemm1 stages

// ---------------- scratch (no allocations allowed) ----------------
__device__ float g_scale[128];            // g/||v|| for U1 (0..63) and U2 (64..127)
__device__ float g_bias[128];             // b1 ‖ b2
__device__ __nv_bfloat16 g_Bhi[128 * VD]; // weight rows hi (U1 ‖ U2)
__device__ __nv_bfloat16 g_Blo[128 * VD]; // weight rows lo
__device__ float g_LR[MTOT * 128];        // relu(V@Wcat^T + b): cols 0..63 right(U1), 64..127 left(U2)
__device__ float g_D[BB * NN];            // per-row rsqrt diag
__device__ float g_U4[BB * 4 * 64];       // 4-way partial u per batch
__device__ float g_S[BB * NN];            // per-batch column means of uncorr
__device__ float g_feats4[4 * BB * VD];   // 4-way m-split partials of feats
__device__ float g_P[8 * BB * EMB];       // split-K partials for final GEMM

// ---------------- Kernel A: weight-norm scale/bias prep ----------------
__global__ void k_prep(const float* __restrict__ U1v, const float* __restrict__ U1g,
                       const float* __restrict__ U1b, const float* __restrict__ U2v,
                       const float* __restrict__ U2g, const float* __restrict__ U2b)
{
    int w = blockIdx.x * 4 + (threadIdx.x >> 5);   // 0..127
    int lane = threadIdx.x & 31;
    const float* v = (w < 64) ? (U1v + w * VD) : (U2v + (w - 64) * VD);
    float ss = 0.f;
    for (int j = lane; j < VD; j += 32) { float x = v[j]; ss = fmaf(x, x, ss); }
    #pragma unroll
    for (int o = 16; o > 0; o >>= 1) ss += __shfl_xor_sync(0xffffffffu, ss, o);
    if (lane == 0) {
        float gg = (w < 64) ? U1g[w] : U2g[w - 64];
        float bb = (w < 64) ? U1b[w] : U2b[w - 64];
        g_scale[w] = gg / sqrtf(ss);
        g_bias[w]  = bb;
    }
}

// ---------------- Kernel A2: split weight rows into bf16 hi/lo ----------------
__global__ void k_convB(const float* __restrict__ U1v, const float* __restrict__ U2v)
{
    int idx = blockIdx.x * 256 + threadIdx.x;      // 0 .. 128*2048-1
    int row = idx >> 11, col = idx & 2047;
    float x = (row < 64) ? U1v[row * VD + col] : U2v[(row - 64) * VD + col];
    __nv_bfloat16 h = __float2bfloat16(x);
    __nv_bfloat16 l = __float2bfloat16(x - __bfloat162float(h));
    g_Bhi[idx] = h;
    g_Blo[idx] = l;
}

// ---------------- mma helpers ----------------
__device__ __forceinline__ void ldsm4(uint32_t* r, uint32_t a) {
    asm volatile("ldmatrix.sync.aligned.m8n8.x4.shared.b16 {%0,%1,%2,%3}, [%4];"
                 : "=r"(r[0]), "=r"(r[1]), "=r"(r[2]), "=r"(r[3]) : "r"(a));
}
__device__ __forceinline__ void mma16816(float* d, const uint32_t* a, const uint32_t* b) {
    asm volatile("mma.sync.aligned.m16n8k16.row.col.f32.bf16.bf16.f32 "
                 "{%0,%1,%2,%3},{%4,%5,%6,%7},{%8,%9},{%0,%1,%2,%3};"
                 : "+f"(d[0]), "+f"(d[1]), "+f"(d[2]), "+f"(d[3])
                 : "r"(a[0]), "r"(a[1]), "r"(a[2]), "r"(a[3]), "r"(b[0]), "r"(b[1]));
}
__device__ __forceinline__ void cp16(uint32_t dst, const void* src) {
    asm volatile("cp.async.ca.shared.global [%0], [%1], 16;" :: "r"(dst), "l"(src));
}
__device__ __forceinline__ unsigned bf2bits(__nv_bfloat162 h) {
    return *reinterpret_cast<unsigned*>(&h);
}

// ---------------- Kernel B: GEMM1 on tensor cores (split-bf16, deep pipeline) ----------------
// C[16384,128] = relu( (A[16384,2048] @ Wcat[128,2048]^T) * scale + bias )
// BM=64, BN=128, BK=16. 8 warps as 2(M)x4(N): warp tile M32 x N32.
// A: fp32 LDG (2-stage reg lookahead) -> split hi/lo -> smem (2 bufs).
// B: bf16 hi/lo via cp.async, 3-slot ring, wait_group 1 (2-stage lookahead).
// Products: Ahi*Bhi + Ahi*Blo + Alo*Bhi (fp32 accumulate).
#define AST 24   // smem row stride in bf16 (16 data + 8 pad; conflict-free ldmatrix)
__global__ __launch_bounds__(256, 2) void k_gemm1(const float* __restrict__ A)
{
    __shared__ __nv_bfloat16 sAh[2][64 * AST], sAl[2][64 * AST];
    __shared__ __nv_bfloat16 sBh[3][128 * AST], sBl[3][128 * AST];

    const int t = threadIdx.x, lane = t & 31, warp = t >> 5;
    const int wy = warp >> 2;           // 0..1  (M half, 32 rows)
    const int wx = warp & 3;            // 0..3  (N quarter, 32 cols)
    const int blockRow = blockIdx.x * 64;

    // load roles
    const int arow = t >> 2, ak = (t & 3) * 4;    // A: 64 rows x 4 floats/thread
    const int bn = t >> 1, bk = (t & 1) * 8;      // B: 128 rows x 8 bf16/thread/matrix
    const float* Ap = A + (size_t)(blockRow + arow) * VD + ak;
    const __nv_bfloat16* Bhp = g_Bhi + bn * VD + bk;
    const __nv_bfloat16* Blp = g_Blo + bn * VD + bk;

    uint32_t uAh[2], uAl[2], uBh[3], uBl[3];
    #pragma unroll
    for (int i = 0; i < 2; i++) {
        uAh[i] = (uint32_t)__cvta_generic_to_shared(&sAh[i][0]);
        uAl[i] = (uint32_t)__cvta_generic_to_shared(&sAl[i][0]);
    }
    #pragma unroll
    for (int i = 0; i < 3; i++) {
        uBh[i] = (uint32_t)__cvta_generic_to_shared(&sBh[i][0]);
        uBl[i] = (uint32_t)__cvta_generic_to_shared(&sBl[i][0]);
    }
    const uint32_t bOff = (uint32_t)(bn * AST + bk) * 2;
    const uint32_t aStOff = (uint32_t)(arow * AST + ak);   // element offset for A STS

    float acc[2][4][4];
    #pragma unroll
    for (int mi = 0; mi < 2; mi++)
        #pragma unroll
        for (int nt = 0; nt < 4; nt++)
            #pragma unroll
            for (int j = 0; j < 4; j++) acc[mi][nt][j] = 0.f;

    // ---- prologue ----
    cp16(uBh[0] + bOff, Bhp);
    cp16(uBl[0] + bOff, Blp);
    asm volatile("cp.async.commit_group;");
    cp16(uBh[1] + bOff, Bhp + 16);
    cp16(uBl[1] + bOff, Blp + 16);
    asm volatile("cp.async.commit_group;");

    float4 av = *(const float4*)Ap;  // A(0)
    {
        __nv_bfloat162 h01 = __floats2bfloat162_rn(av.x, av.y);
        __nv_bfloat162 h23 = __floats2bfloat162_rn(av.z, av.w);
        float2 f01 = __bfloat1622float2(h01), f23 = __bfloat1622float2(h23);
        __nv_bfloat162 l01 = __floats2bfloat162_rn(av.x - f01.x, av.y - f01.y);
        __nv_bfloat162 l23 = __floats2bfloat162_rn(av.z - f23.x, av.w - f23.y);
        uint2 hu; hu.x = bf2bits(h01); hu.y = bf2bits(h23);
        uint2 lu; lu.x = bf2bits(l01); lu.y = bf2bits(l23);
        *(uint2*)&sAh[0][aStOff] = hu;
        *(uint2*)&sAl[0][aStOff] = lu;
    }
    float4 av_cur = *(const float4*)(Ap + 16);  // A(1)
    asm volatile("cp.async.wait_group 1;");
    __syncthreads();

    // per-warp ldmatrix element offsets (x2 for bytes applied below)
    const uint32_t aLdBase = (uint32_t)((wy * 32 + (lane & 15)) * AST + ((lane >> 4) << 3)) * 2;
    const uint32_t bLdBase = (uint32_t)((wx * 32 + (lane & 7) + ((lane >> 4) << 3)) * AST
                                        + (((lane >> 3) & 1) << 3)) * 2;
    const uint32_t mStep = (uint32_t)(16 * AST * 2);  // 16 rows

    for (int s = 0; s < NSG; ++s) {
        const int sl = s % 3, slp = (s + 2) % 3, ab = s & 1;
        if (s + 2 < NSG) {
            cp16(uBh[slp] + bOff, Bhp + (s + 2) * 16);
            cp16(uBl[slp] + bOff, Blp + (s + 2) * 16);
        }
        asm volatile("cp.async.commit_group;");

        // fragment loads for stage s
        uint32_t ah[2][4], al[2][4], bh[2][4], bl[2][4];
        #pragma unroll
        for (int mi = 0; mi < 2; mi++) {
            ldsm4(ah[mi], uAh[ab] + aLdBase + mi * mStep);
            ldsm4(al[mi], uAl[ab] + aLdBase + mi * mStep);
        }
        #pragma unroll
        for (int nj = 0; nj < 2; nj++) {
            ldsm4(bh[nj], uBh[sl] + bLdBase + nj * mStep);
            ldsm4(bl[nj], uBl[sl] + bLdBase + nj * mStep);
        }

        float4 av_next;
        if (s + 2 < NSG) av_next = *(const float4*)(Ap + (s + 2) * 16);

        if (s + 1 < NSG) {
            __nv_bfloat162 h01 = __floats2bfloat162_rn(av_cur.x, av_cur.y);
            __nv_bfloat162 h23 = __floats2bfloat162_rn(av_cur.z, av_cur.w);
            float2 f01 = __bfloat1622float2(h01), f23 = __bfloat1622float2(h23);
            __nv_bfloat162 l01 = __floats2bfloat162_rn(av_cur.x - f01.x, av_cur.y - f01.y);
            __nv_bfloat162 l23 = __floats2bfloat162_rn(av_cur.z - f23.x, av_cur.w - f23.y);
            uint2 hu; hu.x = bf2bits(h01); hu.y = bf2bits(h23);
            uint2 lu; lu.x = bf2bits(l01); lu.y = bf2bits(l23);
            *(uint2*)&sAh[ab ^ 1][aStOff] = hu;
            *(uint2*)&sAl[ab ^ 1][aStOff] = lu;
        }

        #pragma unroll
        for (int mi = 0; mi < 2; mi++)
            #pragma unroll
            for (int nt = 0; nt < 4; nt++) {
                const int nj = nt >> 1, p = (nt & 1) * 2;
                mma16816(acc[mi][nt], ah[mi], &bh[nj][p]);
                mma16816(acc[mi][nt], ah[mi], &bl[nj][p]);
                mma16816(acc[mi][nt], al[mi], &bh[nj][p]);
            }

        asm volatile("cp.async.wait_group 1;");
        __syncthreads();
        av_cur = av_next;
    }

    // ---- epilogue: scale + bias + relu -> g_LR ----
    #pragma unroll
    for (int mi = 0; mi < 2; mi++) {
        const int r0 = blockRow + wy * 32 + mi * 16 + (lane >> 2);
        #pragma unroll
        for (int nt = 0; nt < 4; nt++) {
            const int col = wx * 32 + nt * 8 + ((lane & 3) << 1);
            const float s0 = g_scale[col], s1 = g_scale[col + 1];
            const float b0 = g_bias[col],  b1 = g_bias[col + 1];
            float2 v;
            v.x = fmaxf(fmaf(acc[mi][nt][0], s0, b0), 0.f);
            v.y = fmaxf(fmaf(acc[mi][nt][1], s1, b1), 0.f);
            *(float2*)&g_LR[(size_t)r0 * 128 + col] = v;
            v.x = fmaxf(fmaf(acc[mi][nt][2], s0, b0), 0.f);
            v.y = fmaxf(fmaf(acc[mi][nt][3], s1, b1), 0.f);
            *(float2*)&g_LR[(size_t)(r0 + 8) * 128 + col] = v;
        }
    }
}

// ---------------- Kernel C1: per-row d + 4-way partial u ----------------
// grid (4, BB), 256 threads; 4 lanes per row.
__global__ __launch_bounds__(256) void k_corrA()
{
    __shared__ float d_s[64];
    __shared__ float upart[4][64];
    const int b = blockIdx.y, q = blockIdx.x, t = threadIdx.x;
    const int row = t >> 2, c = t & 3;
    const int gr = b * NN + q * 64 + row;
    const float* myrow = g_LR + (size_t)gr * 128;

    float dot = 0.f;
    #pragma unroll
    for (int j = 0; j < 4; j++) {
        float4 r = ((const float4*)myrow)[c + j * 4];
        float4 l = ((const float4*)myrow)[16 + c + j * 4];
        dot += r.x * l.x + r.y * l.y + r.z * l.z + r.w * l.w;
    }
    dot += __shfl_xor_sync(0xffffffffu, dot, 1);
    dot += __shfl_xor_sync(0xffffffffu, dot, 2);
    const float dv = rsqrtf(dot + 1e-6f);
    if (c == 0) { d_s[row] = dv; g_D[gr] = dv; }
    __syncthreads();

    const int k = t & 63, g = t >> 6;
    float part = 0.f;
    const float* lb = g_LR + (size_t)(b * NN + q * 64 + g * 16) * 128 + 64 + k;
    #pragma unroll
    for (int n = 0; n < 16; n++)
        part = fmaf(d_s[g * 16 + n], lb[(size_t)n * 128], part);
    upart[g][k] = part;
    __syncthreads();
    if (t < 64)
        g_U4[(b * 4 + q) * 64 + t] = upart[0][t] + upart[1][t] + upart[2][t] + upart[3][t];
}

// ---------------- Kernel C2: s[m] from u, d, right ----------------
__global__ __launch_bounds__(256) void k_corrB()
{
    __shared__ float u_s[64];
    const int b = blockIdx.y, q = blockIdx.x, t = threadIdx.x;
    if (t < 64)
        u_s[t] = g_U4[(b * 4 + 0) * 64 + t] + g_U4[(b * 4 + 1) * 64 + t]
               + g_U4[(b * 4 + 2) * 64 + t] + g_U4[(b * 4 + 3) * 64 + t];
    __syncthreads();
    const int row = t >> 2, c = t & 3;
    const int gr = b * NN + q * 64 + row;
    const float* myrow = g_LR + (size_t)gr * 128;
    float sm = 0.f;
    #pragma unroll
    for (int j = 0; j < 4; j++) {
        float4 r = ((const float4*)myrow)[c * 4 + j];
        sm += u_s[c * 16 + j * 4 + 0] * r.x + u_s[c * 16 + j * 4 + 1] * r.y
            + u_s[c * 16 + j * 4 + 2] * r.z + u_s[c * 16 + j * 4 + 3] * r.w;
    }
    sm += __shfl_xor_sync(0xffffffffu, sm, 1);
    sm += __shfl_xor_sync(0xffffffffu, sm, 2);
    if (c == 0)
        g_S[gr] = 1.f + (1.f / 256.f) - (g_D[gr] * (1.f / 256.f)) * sm;
}

// ---------------- Kernel D: feats partials (m split 4 ways, 512 blocks) ----------------
__global__ __launch_bounds__(256) void k_feats(const float* __restrict__ V)
{
    __shared__ float ss[64];
    const int b = blockIdx.z, q = blockIdx.y;
    const int tid = threadIdx.x;
    if (tid < 64) ss[tid] = g_S[b * NN + q * 64 + tid];
    __syncthreads();
    const int v0 = (blockIdx.x * 256 + tid) * 4;
    const float* base = V + (size_t)b * NN * VD + (size_t)q * 64 * VD + v0;
    float4 acc = make_float4(0.f, 0.f, 0.f, 0.f);
    #pragma unroll 4
    for (int m = 0; m < 64; m++) {
        float4 val = *(const float4*)(base + (size_t)m * VD);
        float sv = ss[m];
        acc.x = fmaf(sv, val.x, acc.x);
        acc.y = fmaf(sv, val.y, acc.y);
        acc.z = fmaf(sv, val.z, acc.z);
        acc.w = fmaf(sv, val.w, acc.w);
    }
    *(float4*)(g_feats4 + (size_t)(q * BB + b) * VD + v0) = acc;
}

// ---------------- Kernel E: split-K GEMM  x = feats @ W^T  ->  partials g_P ----------------
__global__ __launch_bounds__(256) void k_gemm2(const float* __restrict__ W)
{
    __shared__ float sA[32][65];
    __shared__ float sB[32][65];
    const int t = threadIdx.x;
    const int tx = t & 15, ty = t >> 4;
    const int e0 = blockIdx.x * 64;
    const int k0 = blockIdx.y * 256;
    const int lrow = t >> 2, lk = (t & 3) * 8;
    float acc[4][4] = {};

    for (int stage = 0; stage < 8; ++stage) {
        const int kb = k0 + stage * 32;
        float4 a0 = make_float4(0,0,0,0), a1 = make_float4(0,0,0,0);
        #pragma unroll
        for (int p = 0; p < 4; p++) {
            float4 t0 = *(const float4*)(g_feats4 + (size_t)(p * BB + lrow) * VD + kb + lk);
            float4 t1 = *(const float4*)(g_feats4 + (size_t)(p * BB + lrow) * VD + kb + lk + 4);
            a0.x += t0.x; a0.y += t0.y; a0.z += t0.z; a0.w += t0.w;
            a1.x += t1.x; a1.y += t1.y; a1.z += t1.z; a1.w += t1.w;
        }
        float4 w0 = *(const float4*)(W + (size_t)(e0 + lrow) * VD + kb + lk);
        float4 w1 = *(const float4*)(W + (size_t)(e0 + lrow) * VD + kb + lk + 4);
        __syncthreads();
        sA[lk+0][lrow]=a0.x; sA[lk+1][lrow]=a0.y; sA[lk+2][lrow]=a0.z; sA[lk+3][lrow]=a0.w;
        sA[lk+4][lrow]=a1.x; sA[lk+5][lrow]=a1.y; sA[lk+6][lrow]=a1.z; sA[lk+7][lrow]=a1.w;
        sB[lk+0][lrow]=w0.x; sB[lk+1][lrow]=w0.y; sB[lk+2][lrow]=w0.z; sB[lk+3][lrow]=w0.w;
        sB[lk+4][lrow]=w1.x; sB[lk+5][lrow]=w1.y; sB[lk+6][lrow]=w1.z; sB[lk+7][lrow]=w1.w;
        __syncthreads();
        #pragma unroll
        for (int k = 0; k < 32; k++) {
            float av[4], bv[4];
            #pragma unroll
            for (int i = 0; i < 4; i++) av[i] = sA[k][ty * 4 + i];
            #pragma unroll
            for (int j = 0; j < 4; j++) bv[j] = sB[k][tx * 4 + j];
            #pragma unroll
            for (int i = 0; i < 4; i++)
                #pragma unroll
                for (int j = 0; j < 4; j++) acc[i][j] = fmaf(av[i], bv[j], acc[i][j]);
        }
    }
    #pragma unroll
    for (int i = 0; i < 4; i++)
        #pragma unroll
        for (int j = 0; j < 4; j++)
            g_P[(size_t)(blockIdx.y * 64 + ty * 4 + i) * EMB + e0 + tx * 4 + j] = acc[i][j];
}

// ---------------- Kernel F: reduce split-K + BatchNorm (single memory pass) ----------------
__global__ __launch_bounds__(256) void k_bn(const float* __restrict__ b_lin,
                                            const float* __restrict__ gamma,
                                            const float* __restrict__ beta,
                                            float* __restrict__ out)
{
    const int e = blockIdx.x * 256 + threadIdx.x;
    const float bias = b_lin[e];
    float x[BB];
    float sum = 0.f;
    #pragma unroll
    for (int b = 0; b < BB; b++) {
        float v = bias;
        #pragma unroll
        for (int s = 0; s < 8; s++) v += g_P[(size_t)(s * BB + b) * EMB + e];
        x[b] = v; sum += v;
    }
    const float mu = sum * (1.f / BB);
    float sq = 0.f;
    #pragma unroll
    for (int b = 0; b < BB; b++) { float d = x[b] - mu; sq = fmaf(d, d, sq); }
    const float inv = rsqrtf(sq * (1.f / BB) + 1e-5f);
    const float ga = gamma[e] * inv, be = beta[e];
    #pragma unroll
    for (int b = 0; b < BB; b++)
        out[b * EMB + e] = fmaf(ga, x[b] - mu, be);
}

// ---------------- launch ----------------
extern "C" void kernel_launch(void* const* d_in, const int* in_sizes, int n_in,
                              void* d_out, int out_size)
{
    const float* Vmat = (const float*)d_in[0];
    const float* U1v  = (const float*)d_in[1];
    const float* U1g  = (const float*)d_in[2];
    const float* U1b  = (const float*)d_in[3];
    const float* U2v  = (const float*)d_in[4];
    const float* U2g  = (const float*)d_in[5];
    const float* U2b  = (const float*)d_in[6];
    const float* Wl   = (const float*)d_in[7];
    const float* bl   = (const float*)d_in[8];
    const float* gam  = (const float*)d_in[9];
    const float* bet  = (const float*)d_in[10];
    float* out = (float*)d_out;

    k_prep<<<32, 128>>>(U1v, U1g, U1b, U2v, U2g, U2b);
    k_convB<<<(128 * VD) / 256, 256>>>(U1v, U2v);
    k_gemm1<<<MTOT / 64, 256>>>(Vmat);
    k_corrA<<<dim3(4, BB), 256>>>();
    k_corrB<<<dim3(4, BB), 256>>>();
    k_feats<<<dim3(2, 4, BB), 256>>>(Vmat);
    k_gemm2<<<dim3(EMB / 64, 8), 256>>>(Wl);
    k_bn<<<EMB / 256, 256>>>(bl, gam, bet, out);
}

// round 9
// speedup vs baseline: 4.1935x; 1.1436x over previous
#include <cuda_runtime.h>
#include <cuda_bf16.h>
#include <cstdint>

typedef unsigned long long ull;

// Shapes (fixed by the problem)
#define BB    64
#define NN    256
#define VD    2048
#define EMB   1024
#define MTOT  (BB*NN) // 16384
#define NSG   (VD/16) // 128 gemm1 stages

// ---------------- scratch (no allocations allowed) ----------------
__device__ float g_scale[128];            // g/||v|| for U1 (0..63) and U2 (64..127)
__device__ float g_bias[128];             // b1 ‖ b2
__device__ __nv_bfloat16 g_Bhi[128 * VD]; // weight rows hi (U1 ‖ U2)
__device__ __nv_bfloat16 g_Blo[128 * VD]; // weight rows lo
__device__ float g_LR[MTOT * 128];        // relu(V@Wcat^T + b): cols 0..63 right(U1), 64..127 left(U2)
__device__ float g_D[BB * NN];            // per-row rsqrt diag
__device__ float g_U4[BB * 4 * 64];       // 4-way partial u per batch
__device__ float g_feats4[4 * BB * VD];   // 4-way m-split partials of feats
__device__ float g_P[8 * BB * EMB];       // split-K partials for final GEMM

// ---------------- Kernel A: weight-norm prep + bf16 hi/lo split (merged) ----------------
// One block per weight row (128 blocks, 256 threads). Row stays in registers.
__global__ __launch_bounds__(256) void k_prepB(const float* __restrict__ U1v, const float* __restrict__ U1g,
                                               const float* __restrict__ U1b, const float* __restrict__ U2v,
                                               const float* __restrict__ U2g, const float* __restrict__ U2b)
{
    __shared__ float red[8];
    const int w = blockIdx.x;            // 0..127
    const int t = threadIdx.x;
    const float* v = (w < 64) ? (U1v + (size_t)w * VD) : (U2v + (size_t)(w - 64) * VD);

    float x[8];
    float ss = 0.f;
    #pragma unroll
    for (int i = 0; i < 8; i++) { x[i] = v[t + i * 256]; ss = fmaf(x[i], x[i], ss); }
    #pragma unroll
    for (int o = 16; o > 0; o >>= 1) ss += __shfl_xor_sync(0xffffffffu, ss, o);
    if ((t & 31) == 0) red[t >> 5] = ss;
    __syncthreads();
    if (t == 0) {
        float tot = 0.f;
        #pragma unroll
        for (int i = 0; i < 8; i++) tot += red[i];
        float gg = (w < 64) ? U1g[w] : U2g[w - 64];
        float bb = (w < 64) ? U1b[w] : U2b[w - 64];
        g_scale[w] = gg / sqrtf(tot);
        g_bias[w]  = bb;
    }
    #pragma unroll
    for (int i = 0; i < 8; i++) {
        int idx = w * VD + t + i * 256;
        __nv_bfloat16 h = __float2bfloat16(x[i]);
        __nv_bfloat16 l = __float2bfloat16(x[i] - __bfloat162float(h));
        g_Bhi[idx] = h;
        g_Blo[idx] = l;
    }
}

// ---------------- mma helpers ----------------
__device__ __forceinline__ void ldsm4(uint32_t* r, uint32_t a) {
    asm volatile("ldmatrix.sync.aligned.m8n8.x4.shared.b16 {%0,%1,%2,%3}, [%4];"
                 : "=r"(r[0]), "=r"(r[1]), "=r"(r[2]), "=r"(r[3]) : "r"(a));
}
__device__ __forceinline__ void mma16816(float* d, const uint32_t* a, const uint32_t* b) {
    asm volatile("mma.sync.aligned.m16n8k16.row.col.f32.bf16.bf16.f32 "
                 "{%0,%1,%2,%3},{%4,%5,%6,%7},{%8,%9},{%0,%1,%2,%3};"
                 : "+f"(d[0]), "+f"(d[1]), "+f"(d[2]), "+f"(d[3])
                 : "r"(a[0]), "r"(a[1]), "r"(a[2]), "r"(a[3]), "r"(b[0]), "r"(b[1]));
}
__device__ __forceinline__ void cp16(uint32_t dst, const void* src) {
    asm volatile("cp.async.ca.shared.global [%0], [%1], 16;" :: "r"(dst), "l"(src));
}
__device__ __forceinline__ unsigned bf2bits(__nv_bfloat162 h) {
    return *reinterpret_cast<unsigned*>(&h);
}
__device__ __forceinline__ uint2 splitpack(float4 av, uint2& lu) {
    __nv_bfloat162 h01 = __floats2bfloat162_rn(av.x, av.y);
    __nv_bfloat162 h23 = __floats2bfloat162_rn(av.z, av.w);
    float2 f01 = __bfloat1622float2(h01), f23 = __bfloat1622float2(h23);
    __nv_bfloat162 l01 = __floats2bfloat162_rn(av.x - f01.x, av.y - f01.y);
    __nv_bfloat162 l23 = __floats2bfloat162_rn(av.z - f23.x, av.w - f23.y);
    uint2 hu; hu.x = bf2bits(h01); hu.y = bf2bits(h23);
    lu.x = bf2bits(l01); lu.y = bf2bits(l23);
    return hu;
}

// ---------------- Kernel B: GEMM1 on tensor cores (split-bf16, deep pipeline) ----------------
// C[16384,128] = relu( (A[16384,2048] @ Wcat[128,2048]^T) * scale + bias )
// BM=64, BN=128, BK=16. 8 warps as 2(M)x4(N): warp tile M32 x N32.
// A: fp32 LDG ring, issue s+4, STS (hi/lo) at s for s+1 (double-buffered smem).
// B: bf16 hi/lo via cp.async, 4-slot ring, issue s+3, wait_group 2.
// Products: Ahi*Bhi + Ahi*Blo + Alo*Bhi (fp32 accumulate).
#define AST 24             // smem row stride in bf16 (16 data + 8 pad; conflict-free ldmatrix)
#define ABUF_B 3072        // bytes per A buffer (64*24*2)
#define BSLOT_B 6144       // bytes per B slot (128*24*2)
#define G1_SMEM (2*ABUF_B*2 + 4*BSLOT_B*2)   // 61440 bytes
__global__ __launch_bounds__(256, 2) void k_gemm1(const float* __restrict__ A)
{
    extern __shared__ __nv_bfloat16 dsm[];
    __nv_bfloat16* pAh = dsm;                    // 2 x 1536 elems
    __nv_bfloat16* pAl = dsm + 3072;
    const uint32_t sbase = (uint32_t)__cvta_generic_to_shared(dsm);
    const uint32_t uAh = sbase;
    const uint32_t uAl = sbase + 2 * ABUF_B;
    const uint32_t uBh = sbase + 4 * ABUF_B;
    const uint32_t uBl = sbase + 4 * ABUF_B + 4 * BSLOT_B;

    const int t = threadIdx.x, lane = t & 31, warp = t >> 5;
    const int wy = warp >> 2;           // 0..1  (M half, 32 rows)
    const int wx = warp & 3;            // 0..3  (N quarter, 32 cols)
    const int blockRow = blockIdx.x * 64;

    // load roles
    const int arow = t >> 2, ak = (t & 3) * 4;    // A: 64 rows x 4 floats/thread
    const int bn = t >> 1, bk = (t & 1) * 8;      // B: 128 rows x 8 bf16/thread/matrix
    const float* Ap = A + (size_t)(blockRow + arow) * VD + ak;
    const __nv_bfloat16* Bhp = g_Bhi + bn * VD + bk;
    const __nv_bfloat16* Blp = g_Blo + bn * VD + bk;

    const uint32_t bOff = (uint32_t)(bn * AST + bk) * 2;   // bytes within slot
    const uint32_t aStOff = (uint32_t)(arow * AST + ak);   // elements within buffer

    float acc[2][4][4];
    #pragma unroll
    for (int mi = 0; mi < 2; mi++)
        #pragma unroll
        for (int nt = 0; nt < 4; nt++)
            #pragma unroll
            for (int j = 0; j < 4; j++) acc[mi][nt][j] = 0.f;

    // ---- prologue: B stages 0..2 into slots 0..2 (3 groups) ----
    cp16(uBh + 0 * BSLOT_B + bOff, Bhp);
    cp16(uBl + 0 * BSLOT_B + bOff, Blp);
    asm volatile("cp.async.commit_group;");
    cp16(uBh + 1 * BSLOT_B + bOff, Bhp + 16);
    cp16(uBl + 1 * BSLOT_B + bOff, Blp + 16);
    asm volatile("cp.async.commit_group;");
    cp16(uBh + 2 * BSLOT_B + bOff, Bhp + 32);
    cp16(uBl + 2 * BSLOT_B + bOff, Blp + 32);
    asm volatile("cp.async.commit_group;");

    // A stage 0 direct to buffer 0; ring holds stages 1..3
    {
        uint2 lu, hu = splitpack(*(const float4*)Ap, lu);
        *(uint2*)&pAh[aStOff] = hu;
        *(uint2*)&pAl[aStOff] = lu;
    }
    float4 a_sts = *(const float4*)(Ap + 16);   // stage 1
    float4 a_1   = *(const float4*)(Ap + 32);   // stage 2
    float4 a_2   = *(const float4*)(Ap + 48);   // stage 3

    asm volatile("cp.async.wait_group 2;");     // slot 0 ready
    __syncthreads();

    // per-warp ldmatrix byte offsets
    const uint32_t aLdBase = (uint32_t)((wy * 32 + (lane & 15)) * AST + ((lane >> 4) << 3)) * 2;
    const uint32_t bLdBase = (uint32_t)((wx * 32 + (lane & 7) + ((lane >> 4) << 3)) * AST
                                        + (((lane >> 3) & 1) << 3)) * 2;
    const uint32_t mStep = (uint32_t)(16 * AST * 2);  // 16 rows in bytes

    for (int s = 0; s < NSG; ++s) {
        const int sl = s & 3, slp = (s + 3) & 3, ab = s & 1;
        if (s + 3 < NSG) {
            cp16(uBh + slp * BSLOT_B + bOff, Bhp + (s + 3) * 16);
            cp16(uBl + slp * BSLOT_B + bOff, Blp + (s + 3) * 16);
        }
        asm volatile("cp.async.commit_group;");

        // fragment loads for stage s
        uint32_t ah[2][4], al[2][4], bh[2][4], bl[2][4];
        #pragma unroll
        for (int mi = 0; mi < 2; mi++) {
            ldsm4(ah[mi], uAh + ab * ABUF_B + aLdBase + mi * mStep);
            ldsm4(al[mi], uAl + ab * ABUF_B + aLdBase + mi * mStep);
        }
        #pragma unroll
        for (int nj = 0; nj < 2; nj++) {
            ldsm4(bh[nj], uBh + sl * BSLOT_B + bLdBase + nj * mStep);
            ldsm4(bl[nj], uBl + sl * BSLOT_B + bLdBase + nj * mStep);
        }

        // issue A LDG for stage s+4
        float4 a_new;
        if (s + 4 < NSG) a_new = *(const float4*)(Ap + (s + 4) * 16);

        // STS stage s+1 (buffer ab^1)
        if (s + 1 < NSG) {
            uint2 lu, hu = splitpack(a_sts, lu);
            *(uint2*)&pAh[(size_t)(ab ^ 1) * 1536 + aStOff] = hu;
            *(uint2*)&pAl[(size_t)(ab ^ 1) * 1536 + aStOff] = lu;
        }
        a_sts = a_1; a_1 = a_2; a_2 = a_new;

        #pragma unroll
        for (int mi = 0; mi < 2; mi++)
            #pragma unroll
            for (int nt = 0; nt < 4; nt++) {
                const int nj = nt >> 1, p = (nt & 1) * 2;
                mma16816(acc[mi][nt], ah[mi], &bh[nj][p]);
                mma16816(acc[mi][nt], ah[mi], &bl[nj][p]);
                mma16816(acc[mi][nt], al[mi], &bh[nj][p]);
            }

        asm volatile("cp.async.wait_group 2;");
        __syncthreads();
    }

    // ---- epilogue: scale + bias + relu -> g_LR ----
    #pragma unroll
    for (int mi = 0; mi < 2; mi++) {
        const int r0 = blockRow + wy * 32 + mi * 16 + (lane >> 2);
        #pragma unroll
        for (int nt = 0; nt < 4; nt++) {
            const int col = wx * 32 + nt * 8 + ((lane & 3) << 1);
            const float s0 = g_scale[col], s1 = g_scale[col + 1];
            const float b0 = g_bias[col],  b1 = g_bias[col + 1];
            float2 v;
            v.x = fmaxf(fmaf(acc[mi][nt][0], s0, b0), 0.f);
            v.y = fmaxf(fmaf(acc[mi][nt][1], s1, b1), 0.f);
            *(float2*)&g_LR[(size_t)r0 * 128 + col] = v;
            v.x = fmaxf(fmaf(acc[mi][nt][2], s0, b0), 0.f);
            v.y = fmaxf(fmaf(acc[mi][nt][3], s1, b1), 0.f);
            *(float2*)&g_LR[(size_t)(r0 + 8) * 128 + col] = v;
        }
    }
}

// ---------------- Kernel C1: per-row d + 4-way partial u ----------------
// grid (4, BB), 256 threads; 4 lanes per row.
__global__ __launch_bounds__(256) void k_corrA()
{
    __shared__ float d_s[64];
    __shared__ float upart[4][64];
    const int b = blockIdx.y, q = blockIdx.x, t = threadIdx.x;
    const int row = t >> 2, c = t & 3;
    const int gr = b * NN + q * 64 + row;
    const float* myrow = g_LR + (size_t)gr * 128;

    float dot = 0.f;
    #pragma unroll
    for (int j = 0; j < 4; j++) {
        float4 r = ((const float4*)myrow)[c + j * 4];
        float4 l = ((const float4*)myrow)[16 + c + j * 4];
        dot += r.x * l.x + r.y * l.y + r.z * l.z + r.w * l.w;
    }
    dot += __shfl_xor_sync(0xffffffffu, dot, 1);
    dot += __shfl_xor_sync(0xffffffffu, dot, 2);
    const float dv = rsqrtf(dot + 1e-6f);
    if (c == 0) { d_s[row] = dv; g_D[gr] = dv; }
    __syncthreads();

    const int k = t & 63, g = t >> 6;
    float part = 0.f;
    const float* lb = g_LR + (size_t)(b * NN + q * 64 + g * 16) * 128 + 64 + k;
    #pragma unroll
    for (int n = 0; n < 16; n++)
        part = fmaf(d_s[g * 16 + n], lb[(size_t)n * 128], part);
    upart[g][k] = part;
    __syncthreads();
    if (t < 64)
        g_U4[(b * 4 + q) * 64 + t] = upart[0][t] + upart[1][t] + upart[2][t] + upart[3][t];
}

// ---------------- Kernel D: s[m] (fused corrB) + feats partials ----------------
// grid (2, 4, BB): x = v-half, y = m-quarter q, z = batch.
__global__ __launch_bounds__(256) void k_featsS(const float* __restrict__ V)
{
    __shared__ float u_s[64];
    __shared__ float ss[64];
    const int b = blockIdx.z, q = blockIdx.y;
    const int t = threadIdx.x;

    if (t < 64)
        u_s[t] = g_U4[(b * 4 + 0) * 64 + t] + g_U4[(b * 4 + 1) * 64 + t]
               + g_U4[(b * 4 + 2) * 64 + t] + g_U4[(b * 4 + 3) * 64 + t];
    __syncthreads();

    {   // s for this block's 64 rows (4 lanes per row)
        const int row = t >> 2, c = t & 3;
        const int gr = b * NN + q * 64 + row;
        const float* myrow = g_LR + (size_t)gr * 128;
        float sm = 0.f;
        #pragma unroll
        for (int j = 0; j < 4; j++) {
            float4 r = ((const float4*)myrow)[c * 4 + j];
            sm += u_s[c * 16 + j * 4 + 0] * r.x + u_s[c * 16 + j * 4 + 1] * r.y
                + u_s[c * 16 + j * 4 + 2] * r.z + u_s[c * 16 + j * 4 + 3] * r.w;
        }
        sm += __shfl_xor_sync(0xffffffffu, sm, 1);
        sm += __shfl_xor_sync(0xffffffffu, sm, 2);
        if (c == 0)
            ss[row] = 1.f + (1.f / 256.f) - (g_D[gr] * (1.f / 256.f)) * sm;
    }
    __syncthreads();

    const int v0 = (blockIdx.x * 256 + t) * 4;
    const float* base = V + (size_t)b * NN * VD + (size_t)q * 64 * VD + v0;
    float4 acc = make_float4(0.f, 0.f, 0.f, 0.f);
    #pragma unroll 4
    for (int m = 0; m < 64; m++) {
        float4 val = *(const float4*)(base + (size_t)m * VD);
        float sv = ss[m];
        acc.x = fmaf(sv, val.x, acc.x);
        acc.y = fmaf(sv, val.y, acc.y);
        acc.z = fmaf(sv, val.z, acc.z);
        acc.w = fmaf(sv, val.w, acc.w);
    }
    *(float4*)(g_feats4 + (size_t)(q * BB + b) * VD + v0) = acc;
}

// ---------------- Kernel E: split-K GEMM  x = feats @ W^T  ->  partials g_P ----------------
__global__ __launch_bounds__(256) void k_gemm2(const float* __restrict__ W)
{
    __shared__ float sA[32][65];
    __shared__ float sB[32][65];
    const int t = threadIdx.x;
    const int tx = t & 15, ty = t >> 4;
    const int e0 = blockIdx.x * 64;
    const int k0 = blockIdx.y * 256;
    const int lrow = t >> 2, lk = (t & 3) * 8;
    float acc[4][4] = {};

    for (int stage = 0; stage < 8; ++stage) {
        const int kb = k0 + stage * 32;
        float4 a0 = make_float4(0,0,0,0), a1 = make_float4(0,0,0,0);
        #pragma unroll
        for (int p = 0; p < 4; p++) {
            float4 t0 = *(const float4*)(g_feats4 + (size_t)(p * BB + lrow) * VD + kb + lk);
            float4 t1 = *(const float4*)(g_feats4 + (size_t)(p * BB + lrow) * VD + kb + lk + 4);
            a0.x += t0.x; a0.y += t0.y; a0.z += t0.z; a0.w += t0.w;
            a1.x += t1.x; a1.y += t1.y; a1.z += t1.z; a1.w += t1.w;
        }
        float4 w0 = *(const float4*)(W + (size_t)(e0 + lrow) * VD + kb + lk);
        float4 w1 = *(const float4*)(W + (size_t)(e0 + lrow) * VD + kb + lk + 4);
        __syncthreads();
        sA[lk+0][lrow]=a0.x; sA[lk+1][lrow]=a0.y; sA[lk+2][lrow]=a0.z; sA[lk+3][lrow]=a0.w;
        sA[lk+4][lrow]=a1.x; sA[lk+5][lrow]=a1.y; sA[lk+6][lrow]=a1.z; sA[lk+7][lrow]=a1.w;
        sB[lk+0][lrow]=w0.x; sB[lk+1][lrow]=w0.y; sB[lk+2][lrow]=w0.z; sB[lk+3][lrow]=w0.w;
        sB[lk+4][lrow]=w1.x; sB[lk+5][lrow]=w1.y; sB[lk+6][lrow]=w1.z; sB[lk+7][lrow]=w1.w;
        __syncthreads();
        #pragma unroll
        for (int k = 0; k < 32; k++) {
            float av[4], bv[4];
            #pragma unroll
            for (int i = 0; i < 4; i++) av[i] = sA[k][ty * 4 + i];
            #pragma unroll
            for (int j = 0; j < 4; j++) bv[j] = sB[k][tx * 4 + j];
            #pragma unroll
            for (int i = 0; i < 4; i++)
                #pragma unroll
                for (int j = 0; j < 4; j++) acc[i][j] = fmaf(av[i], bv[j], acc[i][j]);
        }
    }
    #pragma unroll
    for (int i = 0; i < 4; i++)
        #pragma unroll
        for (int j = 0; j < 4; j++)
            g_P[(size_t)(blockIdx.y * 64 + ty * 4 + i) * EMB + e0 + tx * 4 + j] = acc[i][j];
}

// ---------------- Kernel F: reduce split-K + BatchNorm (single memory pass) ----------------
__global__ __launch_bounds__(256) void k_bn(const float* __restrict__ b_lin,
                                            const float* __restrict__ gamma,
                                            const float* __restrict__ beta,
                                            float* __restrict__ out)
{
    const int e = blockIdx.x * 256 + threadIdx.x;
    const float bias = b_lin[e];
    float x[BB];
    float sum = 0.f;
    #pragma unroll
    for (int b = 0; b < BB; b++) {
        float v = bias;
        #pragma unroll
        for (int s = 0; s < 8; s++) v += g_P[(size_t)(s * BB + b) * EMB + e];
        x[b] = v; sum += v;
    }
    const float mu = sum * (1.f / BB);
    float sq = 0.f;
    #pragma unroll
    for (int b = 0; b < BB; b++) { float d = x[b] - mu; sq = fmaf(d, d, sq); }
    const float inv = rsqrtf(sq * (1.f / BB) + 1e-5f);
    const float ga = gamma[e] * inv, be = beta[e];
    #pragma unroll
    for (int b = 0; b < BB; b++)
        out[b * EMB + e] = fmaf(ga, x[b] - mu, be);
}

// ---------------- launch ----------------
extern "C" void kernel_launch(void* const* d_in, const int* in_sizes, int n_in,
                              void* d_out, int out_size)
{
    const float* Vmat = (const float*)d_in[0];
    const float* U1v  = (const float*)d_in[1];
    const float* U1g  = (const float*)d_in[2];
    const float* U1b  = (const float*)d_in[3];
    const float* U2v  = (const float*)d_in[4];
    const float* U2g  = (const float*)d_in[5];
    const float* U2b  = (const float*)d_in[6];
    const float* Wl   = (const float*)d_in[7];
    const float* bl   = (const float*)d_in[8];
    const float* gam  = (const float*)d_in[9];
    const float* bet  = (const float*)d_in[10];
    float* out = (float*)d_out;

    cudaFuncSetAttribute(k_gemm1, cudaFuncAttributeMaxDynamicSharedMemorySize, G1_SMEM);

    k_prepB<<<128, 256>>>(U1v, U1g, U1b, U2v, U2g, U2b);
    k_gemm1<<<MTOT / 64, 256, G1_SMEM>>>(Vmat);
    k_corrA<<<dim3(4, BB), 256>>>();
    k_featsS<<<dim3(2, 4, BB), 256>>>(Vmat);
    k_gemm2<<<dim3(EMB / 64, 8), 256>>>(Wl);
    k_bn<<<EMB / 256, 256>>>(bl, gam, bet, out);
}

// round 12
// speedup vs baseline: 4.4915x; 1.0710x over previous
#include <cuda_runtime.h>
#include <cuda_fp16.h>
#include <cstdint>

typedef unsigned long long ull;

// Shapes (fixed by the problem)
#define BB    64
#define NN    256
#define VD    2048
#define EMB   1024
#define MTOT  (BB*NN) // 16384
#define NSG   (VD/16) // 128 gemm1 stages

// ---------------- scratch (no allocations allowed) ----------------
__device__ float g_scale[128];            // g/||v|| for U1 (0..63) and U2 (64..127)
__device__ float g_bias[128];             // b1 ‖ b2
__device__ __half g_Bh[128 * VD];         // weight rows, fp16 (U1 ‖ U2)
__device__ float g_LR[MTOT * 128];        // relu(V@Wcat^T + b): cols 0..63 right(U1), 64..127 left(U2)
__device__ float g_D[BB * NN];            // per-row rsqrt diag
__device__ float g_U4[BB * 4 * 64];       // 4-way partial u per batch
__device__ float g_feats4[4 * BB * VD];   // 4-way m-split partials of feats
__device__ float g_P[8 * BB * EMB];       // split-K partials for final GEMM

// ---------------- Kernel A: weight-norm prep + fp16 weight cast (merged) ----------------
// One block per weight row (128 blocks, 256 threads). Row stays in registers.
__global__ __launch_bounds__(256) void k_prepB(const float* __restrict__ U1v, const float* __restrict__ U1g,
                                               const float* __restrict__ U1b, const float* __restrict__ U2v,
                                               const float* __restrict__ U2g, const float* __restrict__ U2b)
{
    __shared__ float red[8];
    const int w = blockIdx.x;            // 0..127
    const int t = threadIdx.x;
    const float* v = (w < 64) ? (U1v + (size_t)w * VD) : (U2v + (size_t)(w - 64) * VD);

    float x[8];
    float ss = 0.f;
    #pragma unroll
    for (int i = 0; i < 8; i++) { x[i] = v[t + i * 256]; ss = fmaf(x[i], x[i], ss); }
    #pragma unroll
    for (int o = 16; o > 0; o >>= 1) ss += __shfl_xor_sync(0xffffffffu, ss, o);
    if ((t & 31) == 0) red[t >> 5] = ss;
    __syncthreads();
    if (t == 0) {
        float tot = 0.f;
        #pragma unroll
        for (int i = 0; i < 8; i++) tot += red[i];
        float gg = (w < 64) ? U1g[w] : U2g[w - 64];
        float bb = (w < 64) ? U1b[w] : U2b[w - 64];
        g_scale[w] = gg / sqrtf(tot);
        g_bias[w]  = bb;
    }
    #pragma unroll
    for (int i = 0; i < 8; i++)
        g_Bh[w * VD + t + i * 256] = __float2half_rn(x[i]);
}

// ---------------- mma helpers ----------------
__device__ __forceinline__ void ldsm4(uint32_t* r, uint32_t a) {
    asm volatile("ldmatrix.sync.aligned.m8n8.x4.shared.b16 {%0,%1,%2,%3}, [%4];"
                 : "=r"(r[0]), "=r"(r[1]), "=r"(r[2]), "=r"(r[3]) : "r"(a));
}
__device__ __forceinline__ void mma16816(float* d, const uint32_t* a, const uint32_t* b) {
    asm volatile("mma.sync.aligned.m16n8k16.row.col.f32.f16.f16.f32 "
                 "{%0,%1,%2,%3},{%4,%5,%6,%7},{%8,%9},{%0,%1,%2,%3};"
                 : "+f"(d[0]), "+f"(d[1]), "+f"(d[2]), "+f"(d[3])
                 : "r"(a[0]), "r"(a[1]), "r"(a[2]), "r"(a[3]), "r"(b[0]), "r"(b[1]));
}
__device__ __forceinline__ void cp16(uint32_t dst, const void* src) {
    asm volatile("cp.async.ca.shared.global [%0], [%1], 16;" :: "r"(dst), "l"(src));
}
__device__ __forceinline__ unsigned h2bits(__half2 h) {
    return *reinterpret_cast<unsigned*>(&h);
}
// fp32 -> fp16 hi/lo split, packed pairs
__device__ __forceinline__ uint2 splitpackh(float4 av, uint2& lu) {
    __half2 h01 = __float22half2_rn(make_float2(av.x, av.y));
    __half2 h23 = __float22half2_rn(make_float2(av.z, av.w));
    float2 f01 = __half22float2(h01), f23 = __half22float2(h23);
    __half2 l01 = __float22half2_rn(make_float2(av.x - f01.x, av.y - f01.y));
    __half2 l23 = __float22half2_rn(make_float2(av.z - f23.x, av.w - f23.y));
    uint2 hu; hu.x = h2bits(h01); hu.y = h2bits(h23);
    lu.x = h2bits(l01); lu.y = h2bits(l23);
    return hu;
}

// ---------------- Kernel B: GEMM1 on tensor cores (fp16 2-product split) ----------------
// C[16384,128] = relu( (A[16384,2048] @ Wcat[128,2048]^T) * scale + bias )
// BM=64, BN=128, BK=16. 8 warps as 2(M)x4(N): warp tile M32 x N32.
// A: fp32 LDG ring (issue s+4), fp16 hi/lo split -> smem (2 bufs).
// B: fp16 via cp.async, 4-slot ring, issue s+3, wait_group 2.
// Products: Ah*Bh + Al*Bh (fp32 accumulate). Error ~ A*(B - Bh) ~ 2^-12 rel.
#define AST 24             // smem row stride in halves (16 data + 8 pad; conflict-free ldmatrix)
__global__ __launch_bounds__(256, 2) void k_gemm1(const float* __restrict__ A)
{
    __shared__ __half sAh[2][64 * AST];
    __shared__ __half sAl[2][64 * AST];
    __shared__ __half sBh[4][128 * AST];

    const int t = threadIdx.x, lane = t & 31, warp = t >> 5;
    const int wy = warp >> 2;           // 0..1  (M half, 32 rows)
    const int wx = warp & 3;            // 0..3  (N quarter, 32 cols)
    const int blockRow = blockIdx.x * 64;

    // load roles
    const int arow = t >> 2, ak = (t & 3) * 4;    // A: 64 rows x 4 floats/thread
    const int bn = t >> 1, bk = (t & 1) * 8;      // B: 128 rows x 8 halves/thread
    const float* Ap = A + (size_t)(blockRow + arow) * VD + ak;
    const __half* Bhp = g_Bh + bn * VD + bk;

    uint32_t uAh[2], uAl[2], uBh[4];
    #pragma unroll
    for (int i = 0; i < 2; i++) {
        uAh[i] = (uint32_t)__cvta_generic_to_shared(&sAh[i][0]);
        uAl[i] = (uint32_t)__cvta_generic_to_shared(&sAl[i][0]);
    }
    #pragma unroll
    for (int i = 0; i < 4; i++)
        uBh[i] = (uint32_t)__cvta_generic_to_shared(&sBh[i][0]);

    const uint32_t bOff = (uint32_t)(bn * AST + bk) * 2;   // bytes within slot
    const uint32_t aStOff = (uint32_t)(arow * AST + ak);   // elements within buffer

    float acc[2][4][4];
    #pragma unroll
    for (int mi = 0; mi < 2; mi++)
        #pragma unroll
        for (int nt = 0; nt < 4; nt++)
            #pragma unroll
            for (int j = 0; j < 4; j++) acc[mi][nt][j] = 0.f;

    // ---- prologue: B stages 0..2 into slots 0..2 (3 groups) ----
    cp16(uBh[0] + bOff, Bhp);
    asm volatile("cp.async.commit_group;");
    cp16(uBh[1] + bOff, Bhp + 16);
    asm volatile("cp.async.commit_group;");
    cp16(uBh[2] + bOff, Bhp + 32);
    asm volatile("cp.async.commit_group;");

    // A stage 0 direct to buffer 0; ring holds stages 1..3
    {
        uint2 lu, hu = splitpackh(*(const float4*)Ap, lu);
        *(uint2*)&sAh[0][aStOff] = hu;
        *(uint2*)&sAl[0][aStOff] = lu;
    }
    float4 a_sts = *(const float4*)(Ap + 16);   // stage 1
    float4 a_1   = *(const float4*)(Ap + 32);   // stage 2
    float4 a_2   = *(const float4*)(Ap + 48);   // stage 3

    asm volatile("cp.async.wait_group 2;");     // slot 0 ready
    __syncthreads();

    // per-warp ldmatrix byte offsets
    const uint32_t aLdBase = (uint32_t)((wy * 32 + (lane & 15)) * AST + ((lane >> 4) << 3)) * 2;
    const uint32_t bLdBase = (uint32_t)((wx * 32 + (lane & 7) + ((lane >> 4) << 3)) * AST
                                        + (((lane >> 3) & 1) << 3)) * 2;
    const uint32_t mStep = (uint32_t)(16 * AST * 2);  // 16 rows in bytes

    for (int s = 0; s < NSG; ++s) {
        const int sl = s & 3, slp = (s + 3) & 3, ab = s & 1;
        if (s + 3 < NSG)
            cp16(uBh[slp] + bOff, Bhp + (s + 3) * 16);
        asm volatile("cp.async.commit_group;");

        // fragment loads for stage s
        uint32_t ah[2][4], al[2][4], bh[2][4];
        #pragma unroll
        for (int mi = 0; mi < 2; mi++) {
            ldsm4(ah[mi], uAh[ab] + aLdBase + mi * mStep);
            ldsm4(al[mi], uAl[ab] + aLdBase + mi * mStep);
        }
        #pragma unroll
        for (int nj = 0; nj < 2; nj++)
            ldsm4(bh[nj], uBh[sl] + bLdBase + nj * mStep);

        // issue A LDG for stage s+4
        float4 a_new;
        if (s + 4 < NSG) a_new = *(const float4*)(Ap + (s + 4) * 16);

        // STS stage s+1 (buffer ab^1)
        if (s + 1 < NSG) {
            uint2 lu, hu = splitpackh(a_sts, lu);
            *(uint2*)&sAh[ab ^ 1][aStOff] = hu;
            *(uint2*)&sAl[ab ^ 1][aStOff] = lu;
        }
        a_sts = a_1; a_1 = a_2; a_2 = a_new;

        #pragma unroll
        for (int mi = 0; mi < 2; mi++)
            #pragma unroll
            for (int nt = 0; nt < 4; nt++) {
                const int nj = nt >> 1, p = (nt & 1) * 2;
                mma16816(acc[mi][nt], ah[mi], &bh[nj][p]);
                mma16816(acc[mi][nt], al[mi], &bh[nj][p]);
            }

        asm volatile("cp.async.wait_group 2;");
        __syncthreads();
    }

    // ---- epilogue: scale + bias + relu -> g_LR ----
    #pragma unroll
    for (int mi = 0; mi < 2; mi++) {
        const int r0 = blockRow + wy * 32 + mi * 16 + (lane >> 2);
        #pragma unroll
        for (int nt = 0; nt < 4; nt++) {
            const int col = wx * 32 + nt * 8 + ((lane & 3) << 1);
            const float s0 = g_scale[col], s1 = g_scale[col + 1];
            const float b0 = g_bias[col],  b1 = g_bias[col + 1];
            float2 v;
            v.x = fmaxf(fmaf(acc[mi][nt][0], s0, b0), 0.f);
            v.y = fmaxf(fmaf(acc[mi][nt][1], s1, b1), 0.f);
            *(float2*)&g_LR[(size_t)r0 * 128 + col] = v;
            v.x = fmaxf(fmaf(acc[mi][nt][2], s0, b0), 0.f);
            v.y = fmaxf(fmaf(acc[mi][nt][3], s1, b1), 0.f);
            *(float2*)&g_LR[(size_t)(r0 + 8) * 128 + col] = v;
        }
    }
}

// ---------------- Kernel C1: per-row d + 4-way partial u ----------------
// grid (4, BB), 256 threads; 4 lanes per row.
__global__ __launch_bounds__(256) void k_corrA()
{
    __shared__ float d_s[64];
    __shared__ float upart[4][64];
    const int b = blockIdx.y, q = blockIdx.x, t = threadIdx.x;
    const int row = t >> 2, c = t & 3;
    const int gr = b * NN + q * 64 + row;
    const float* myrow = g_LR + (size_t)gr * 128;

    float dot = 0.f;
    #pragma unroll
    for (int j = 0; j < 4; j++) {
        float4 r = ((const float4*)myrow)[c + j * 4];
        float4 l = ((const float4*)myrow)[16 + c + j * 4];
        dot += r.x * l.x + r.y * l.y + r.z * l.z + r.w * l.w;
    }
    dot += __shfl_xor_sync(0xffffffffu, dot, 1);
    dot += __shfl_xor_sync(0xffffffffu, dot, 2);
    const float dv = rsqrtf(dot + 1e-6f);
    if (c == 0) { d_s[row] = dv; g_D[gr] = dv; }
    __syncthreads();

    const int k = t & 63, g = t >> 6;
    float part = 0.f;
    const float* lb = g_LR + (size_t)(b * NN + q * 64 + g * 16) * 128 + 64 + k;
    #pragma unroll
    for (int n = 0; n < 16; n++)
        part = fmaf(d_s[g * 16 + n], lb[(size_t)n * 128], part);
    upart[g][k] = part;
    __syncthreads();
    if (t < 64)
        g_U4[(b * 4 + q) * 64 + t] = upart[0][t] + upart[1][t] + upart[2][t] + upart[3][t];
}

// ---------------- Kernel D: s[m] (fused corrB) + feats partials ----------------
// grid (2, 4, BB): x = v-half, y = m-quarter q, z = batch.
__global__ __launch_bounds__(256) void k_featsS(const float* __restrict__ V)
{
    __shared__ float u_s[64];
    __shared__ float ss[64];
    const int b = blockIdx.z, q = blockIdx.y;
    const int t = threadIdx.x;

    if (t < 64)
        u_s[t] = g_U4[(b * 4 + 0) * 64 + t] + g_U4[(b * 4 + 1) * 64 + t]
               + g_U4[(b * 4 + 2) * 64 + t] + g_U4[(b * 4 + 3) * 64 + t];
    __syncthreads();

    {   // s for this block's 64 rows (4 lanes per row)
        const int row = t >> 2, c = t & 3;
        const int gr = b * NN + q * 64 + row;
        const float* myrow = g_LR + (size_t)gr * 128;
        float sm = 0.f;
        #pragma unroll
        for (int j = 0; j < 4; j++) {
            float4 r = ((const float4*)myrow)[c * 4 + j];
            sm += u_s[c * 16 + j * 4 + 0] * r.x + u_s[c * 16 + j * 4 + 1] * r.y
                + u_s[c * 16 + j * 4 + 2] * r.z + u_s[c * 16 + j * 4 + 3] * r.w;
        }
        sm += __shfl_xor_sync(0xffffffffu, sm, 1);
        sm += __shfl_xor_sync(0xffffffffu, sm, 2);
        if (c == 0)
            ss[row] = 1.f + (1.f / 256.f) - (g_D[gr] * (1.f / 256.f)) * sm;
    }
    __syncthreads();

    const int v0 = (blockIdx.x * 256 + t) * 4;
    const float* base = V + (size_t)b * NN * VD + (size_t)q * 64 * VD + v0;
    float4 acc = make_float4(0.f, 0.f, 0.f, 0.f);
    #pragma unroll 4
    for (int m = 0; m < 64; m++) {
        float4 val = *(const float4*)(base + (size_t)m * VD);
        float sv = ss[m];
        acc.x = fmaf(sv, val.x, acc.x);
        acc.y = fmaf(sv, val.y, acc.y);
        acc.z = fmaf(sv, val.z, acc.z);
        acc.w = fmaf(sv, val.w, acc.w);
    }
    *(float4*)(g_feats4 + (size_t)(q * BB + b) * VD + v0) = acc;
}

// ---------------- Kernel E: split-K GEMM  x = feats @ W^T  ->  partials g_P ----------------
__global__ __launch_bounds__(256) void k_gemm2(const float* __restrict__ W)
{
    __shared__ float sA[32][65];
    __shared__ float sB[32][65];
    const int t = threadIdx.x;
    const int tx = t & 15, ty = t >> 4;
    const int e0 = blockIdx.x * 64;
    const int k0 = blockIdx.y * 256;
    const int lrow = t >> 2, lk = (t & 3) * 8;
    float acc[4][4] = {};

    for (int stage = 0; stage < 8; ++stage) {
        const int kb = k0 + stage * 32;
        float4 a0 = make_float4(0,0,0,0), a1 = make_float4(0,0,0,0);
        #pragma unroll
        for (int p = 0; p < 4; p++) {
            float4 t0 = *(const float4*)(g_feats4 + (size_t)(p * BB + lrow) * VD + kb + lk);
            float4 t1 = *(const float4*)(g_feats4 + (size_t)(p * BB + lrow) * VD + kb + lk + 4);
            a0.x += t0.x; a0.y += t0.y; a0.z += t0.z; a0.w += t0.w;
            a1.x += t1.x; a1.y += t1.y; a1.z += t1.z; a1.w += t1.w;
        }
        float4 w0 = *(const float4*)(W + (size_t)(e0 + lrow) * VD + kb + lk);
        float4 w1 = *(const float4*)(W + (size_t)(e0 + lrow) * VD + kb + lk + 4);
        __syncthreads();
        sA[lk+0][lrow]=a0.x; sA[lk+1][lrow]=a0.y; sA[lk+2][lrow]=a0.z; sA[lk+3][lrow]=a0.w;
        sA[lk+4][lrow]=a1.x; sA[lk+5][lrow]=a1.y; sA[lk+6][lrow]=a1.z; sA[lk+7][lrow]=a1.w;
        sB[lk+0][lrow]=w0.x; sB[lk+1][lrow]=w0.y; sB[lk+2][lrow]=w0.z; sB[lk+3][lrow]=w0.w;
        sB[lk+4][lrow]=w1.x; sB[lk+5][lrow]=w1.y; sB[lk+6][lrow]=w1.z; sB[lk+7][lrow]=w1.w;
        __syncthreads();
        #pragma unroll
        for (int k = 0; k < 32; k++) {
            float av[4], bv[4];
            #pragma unroll
            for (int i = 0; i < 4; i++) av[i] = sA[k][ty * 4 + i];
            #pragma unroll
            for (int j = 0; j < 4; j++) bv[j] = sB[k][tx * 4 + j];
            #pragma unroll
            for (int i = 0; i < 4; i++)
                #pragma unroll
                for (int j = 0; j < 4; j++) acc[i][j] = fmaf(av[i], bv[j], acc[i][j]);
        }
    }
    #pragma unroll
    for (int i = 0; i < 4; i++)
        #pragma unroll
        for (int j = 0; j < 4; j++)
            g_P[(size_t)(blockIdx.y * 64 + ty * 4 + i) * EMB + e0 + tx * 4 + j] = acc[i][j];
}

// ---------------- Kernel F: reduce split-K + BatchNorm (single memory pass) ----------------
__global__ __launch_bounds__(256) void k_bn(const float* __restrict__ b_lin,
                                            const float* __restrict__ gamma,
                                            const float* __restrict__ beta,
                                            float* __restrict__ out)
{
    const int e = blockIdx.x * 256 + threadIdx.x;
    const float bias = b_lin[e];
    float x[BB];
    float sum = 0.f;
    #pragma unroll
    for (int b = 0; b < BB; b++) {
        float v = bias;
        #pragma unroll
        for (int s = 0; s < 8; s++) v += g_P[(size_t)(s * BB + b) * EMB + e];
        x[b] = v; sum += v;
    }
    const float mu = sum * (1.f / BB);
    float sq = 0.f;
    #pragma unroll
    for (int b = 0; b < BB; b++) { float d = x[b] - mu; sq = fmaf(d, d, sq); }
    const float inv = rsqrtf(sq * (1.f / BB) + 1e-5f);
    const float ga = gamma[e] * inv, be = beta[e];
    #pragma unroll
    for (int b = 0; b < BB; b++)
        out[b * EMB + e] = fmaf(ga, x[b] - mu, be);
}

// ---------------- launch ----------------
extern "C" void kernel_launch(void* const* d_in, const int* in_sizes, int n_in,
                              void* d_out, int out_size)
{
    const float* Vmat = (const float*)d_in[0];
    const float* U1v  = (const float*)d_in[1];
    const float* U1g  = (const float*)d_in[2];
    const float* U1b  = (const float*)d_in[3];
    const float* U2v  = (const float*)d_in[4];
    const float* U2g  = (const float*)d_in[5];
    const float* U2b  = (const float*)d_in[6];
    const float* Wl   = (const float*)d_in[7];
    const float* bl   = (const float*)d_in[8];
    const float* gam  = (const float*)d_in[9];
    const float* bet  = (const float*)d_in[10];
    float* out = (float*)d_out;

    k_prepB<<<128, 256>>>(U1v, U1g, U1b, U2v, U2g, U2b);
    k_gemm1<<<MTOT / 64, 256>>>(Vmat);
    k_corrA<<<dim3(4, BB), 256>>>();
    k_featsS<<<dim3(2, 4, BB), 256>>>(Vmat);
    k_gemm2<<<dim3(EMB / 64, 8), 256>>>(Wl);
    k_bn<<<EMB / 256, 256>>>(bl, gam, bet, out);
}